// round 2
// baseline (speedup 1.0000x reference)
#include <cuda_runtime.h>
#include <math.h>

// Problem dims (fixed by the reference)
#define Dm    1024           // d_model
#define Sm    1024           // seq len
#define NB    2              // batch
#define NHm   16             // heads
#define DQm   64             // head dim
#define DHm   4096           // ffn hidden
#define NL    6              // layers
#define MROWS (NB*Sm)        // 2048 token rows

// ---------------- scratch (device globals; no allocations allowed) --------
__device__ float g_h  [(size_t)MROWS*Dm];
__device__ float g_q  [(size_t)MROWS*Dm];
__device__ float g_kb [(size_t)MROWS*Dm];
__device__ float g_vb [(size_t)MROWS*Dm];
__device__ float g_ctx[(size_t)MROWS*Dm];
__device__ float g_tmp[(size_t)MROWS*Dm];
__device__ float g_ff [(size_t)MROWS*DHm];

// ---------------- copy x -> h ---------------------------------------------
__global__ void __launch_bounds__(256) copy_kernel(float4* __restrict__ dst,
                                                   const float4* __restrict__ src)
{
    int i = blockIdx.x * 256 + threadIdx.x;
    dst[i] = src[i];
}

// ---------------- SGEMM: C[M,N] = A[M,K] @ B[K,N] + bias, optional ReLU ----
// BM=BN=128, BK=16, 256 threads, 8x8 per-thread microtile.
__global__ void __launch_bounds__(256, 2) sgemm_kernel(
    const float* __restrict__ A, const float* __restrict__ B,
    const float* __restrict__ bias, float* __restrict__ C,
    int M, int N, int K, int relu)
{
    __shared__ float As[16][128];   // transposed: As[k][m]
    __shared__ float Bs[16][128];   // Bs[k][n]

    const int tid = threadIdx.x;
    const int m0 = blockIdx.y * 128;
    const int n0 = blockIdx.x * 128;

    const int arow = tid >> 2;           // 0..63 (two passes of 64 rows)
    const int acol = (tid & 3) << 2;     // 0,4,8,12
    const int brow = tid >> 5;           // 0..7 (two passes of 8 rows)
    const int bcol = (tid & 31) << 2;    // 0..124

    const int tx = tid & 15;             // col group
    const int ty = tid >> 4;             // row group

    float acc[8][8];
#pragma unroll
    for (int i = 0; i < 8; i++)
#pragma unroll
        for (int j = 0; j < 8; j++) acc[i][j] = 0.f;

    const float* Ap = A + (size_t)m0 * K;
    const float* Bp = B + n0;

    for (int k0 = 0; k0 < K; k0 += 16) {
#pragma unroll
        for (int p = 0; p < 2; p++) {
            int r = arow + p * 64;
            float4 va = *(const float4*)(Ap + (size_t)r * K + k0 + acol);
            As[acol + 0][r] = va.x;
            As[acol + 1][r] = va.y;
            As[acol + 2][r] = va.z;
            As[acol + 3][r] = va.w;
        }
#pragma unroll
        for (int p = 0; p < 2; p++) {
            int r = brow + p * 8;
            *(float4*)&Bs[r][bcol] = *(const float4*)(Bp + (size_t)(k0 + r) * N + bcol);
        }
        __syncthreads();

#pragma unroll
        for (int kk = 0; kk < 16; kk++) {
            float af[8], bf[8];
            *(float4*)&af[0] = *(const float4*)&As[kk][ty * 8];
            *(float4*)&af[4] = *(const float4*)&As[kk][ty * 8 + 4];
            *(float4*)&bf[0] = *(const float4*)&Bs[kk][tx * 8];
            *(float4*)&bf[4] = *(const float4*)&Bs[kk][tx * 8 + 4];
#pragma unroll
            for (int i = 0; i < 8; i++)
#pragma unroll
                for (int j = 0; j < 8; j++)
                    acc[i][j] = fmaf(af[i], bf[j], acc[i][j]);
        }
        __syncthreads();
    }

#pragma unroll
    for (int i = 0; i < 8; i++) {
        size_t m = (size_t)(m0 + ty * 8 + i);
#pragma unroll
        for (int j = 0; j < 8; j += 4) {
            int n = n0 + tx * 8 + j;
            float4 v;
            v.x = acc[i][j + 0] + bias[n + 0];
            v.y = acc[i][j + 1] + bias[n + 1];
            v.z = acc[i][j + 2] + bias[n + 2];
            v.w = acc[i][j + 3] + bias[n + 3];
            if (relu) {
                v.x = fmaxf(v.x, 0.f); v.y = fmaxf(v.y, 0.f);
                v.z = fmaxf(v.z, 0.f); v.w = fmaxf(v.w, 0.f);
            }
            *(float4*)(C + m * N + n) = v;
        }
    }
}

// ---------------- Flash attention ------------------------------------------
// grid: (S/64 q-tiles, H, B); block 256 threads (8 warps).
// Warp w owns q-rows [8w, 8w+8). Lane owns score col `lane` (K-tile width 32)
// and output cols {lane, lane+32} (DQ=64).
__global__ void __launch_bounds__(256) attn_kernel(
    const float* __restrict__ Q, const float* __restrict__ K,
    const float* __restrict__ V, const unsigned char* __restrict__ mask,
    float* __restrict__ O)
{
    __shared__ float Qs[64][64];     // [qrow][d]
    __shared__ float Kts[64][33];    // transposed: [d][k] (+1 pad)
    __shared__ float Vs[32][64];     // [k][d]
    __shared__ float Ss[64][32];     // probabilities [qrow][k]

    const int tid = threadIdx.x, w = tid >> 5, lane = tid & 31;
    const int qt = blockIdx.x, h = blockIdx.y, b = blockIdx.z;
    const size_t qbase = ((size_t)b * Sm + qt * 64) * Dm + h * DQm;

    // load Q tile (64x64)
#pragma unroll
    for (int it = 0; it < 4; it++) {
        int i = tid + it * 256;
        int r = i >> 4, c4 = (i & 15) << 2;
        *(float4*)&Qs[r][c4] = *(const float4*)(Q + qbase + (size_t)r * Dm + c4);
    }

    float o0[8], o1[8], mr[8], lr[8];
#pragma unroll
    for (int r = 0; r < 8; r++) { o0[r] = 0.f; o1[r] = 0.f; lr[r] = 0.f; mr[r] = -1e30f; }

    const unsigned char* mrow = mask + ((size_t)b * Sm + qt * 64 + w * 8) * Sm;

    for (int k0 = 0; k0 < Sm; k0 += 32) {
        // load K (transposed) and V tiles
#pragma unroll
        for (int it = 0; it < 2; it++) {
            int i = tid + it * 256;
            int kk = i >> 4, c4 = (i & 15) << 2;
            size_t gb = ((size_t)b * Sm + k0 + kk) * Dm + h * DQm;
            float4 kv = *(const float4*)(K + gb + c4);
            Kts[c4 + 0][kk] = kv.x;
            Kts[c4 + 1][kk] = kv.y;
            Kts[c4 + 2][kk] = kv.z;
            Kts[c4 + 3][kk] = kv.w;
            *(float4*)&Vs[kk][c4] = *(const float4*)(V + gb + c4);
        }
        __syncthreads();

        // S[r][lane] = Q[r,:] . K[k0+lane,:]
        float s[8];
#pragma unroll
        for (int r = 0; r < 8; r++) s[r] = 0.f;
#pragma unroll
        for (int d4 = 0; d4 < 16; d4++) {
            float kd0 = Kts[d4 * 4 + 0][lane];
            float kd1 = Kts[d4 * 4 + 1][lane];
            float kd2 = Kts[d4 * 4 + 2][lane];
            float kd3 = Kts[d4 * 4 + 3][lane];
#pragma unroll
            for (int r = 0; r < 8; r++) {
                float4 qv = *(const float4*)&Qs[w * 8 + r][d4 * 4];
                s[r] += qv.x * kd0 + qv.y * kd1 + qv.z * kd2 + qv.w * kd3;
            }
        }

        // mask + scale + online softmax (per-warp rows)
#pragma unroll
        for (int r = 0; r < 8; r++) {
            unsigned char mb = mrow[(size_t)r * Sm + k0 + lane];
            float v = mb ? -1e9f : s[r] * 0.125f;   // 1/sqrt(64)
            float mx = v;
#pragma unroll
            for (int off = 16; off; off >>= 1)
                mx = fmaxf(mx, __shfl_xor_sync(0xffffffffu, mx, off));
            float mnew = fmaxf(mr[r], mx);
            float p = __expf(v - mnew);
            float ps = p;
#pragma unroll
            for (int off = 16; off; off >>= 1)
                ps += __shfl_xor_sync(0xffffffffu, ps, off);
            float alpha = __expf(mr[r] - mnew);
            lr[r] = lr[r] * alpha + ps;
            mr[r] = mnew;
            o0[r] *= alpha;
            o1[r] *= alpha;
            Ss[w * 8 + r][lane] = p;
        }
        __syncwarp();

        // O += P @ V
#pragma unroll
        for (int k4 = 0; k4 < 8; k4++) {
            float va0 = Vs[k4 * 4 + 0][lane], vb0 = Vs[k4 * 4 + 0][lane + 32];
            float va1 = Vs[k4 * 4 + 1][lane], vb1 = Vs[k4 * 4 + 1][lane + 32];
            float va2 = Vs[k4 * 4 + 2][lane], vb2 = Vs[k4 * 4 + 2][lane + 32];
            float va3 = Vs[k4 * 4 + 3][lane], vb3 = Vs[k4 * 4 + 3][lane + 32];
#pragma unroll
            for (int r = 0; r < 8; r++) {
                float4 p = *(const float4*)&Ss[w * 8 + r][k4 * 4];
                o0[r] += p.x * va0 + p.y * va1 + p.z * va2 + p.w * va3;
                o1[r] += p.x * vb0 + p.y * vb1 + p.z * vb2 + p.w * vb3;
            }
        }
        __syncthreads();
    }

#pragma unroll
    for (int r = 0; r < 8; r++) {
        float inv = 1.0f / lr[r];
        size_t orow = qbase + (size_t)(w * 8 + r) * Dm;
        O[orow + lane]      = o0[r] * inv;
        O[orow + lane + 32] = o1[r] * inv;
    }
}

// ---------------- fused residual + LayerNorm -------------------------------
// out[row] = LN(x[row] + t[row]) * g + b ; one block per row, 256 thr x 4 elems
__global__ void __launch_bounds__(256) ln_res_kernel(
    const float* __restrict__ x, const float* __restrict__ t,
    const float* __restrict__ g, const float* __restrict__ be,
    float* __restrict__ out)
{
    const int row = blockIdx.x, tid = threadIdx.x;
    const int w = tid >> 5, lane = tid & 31;
    __shared__ float red[8];
    __shared__ float bcast;

    float4 a = ((const float4*)(x + (size_t)row * Dm))[tid];
    float4 bb = ((const float4*)(t + (size_t)row * Dm))[tid];
    float v0 = a.x + bb.x, v1 = a.y + bb.y, v2 = a.z + bb.z, v3 = a.w + bb.w;

    float s = v0 + v1 + v2 + v3;
#pragma unroll
    for (int off = 16; off; off >>= 1) s += __shfl_xor_sync(0xffffffffu, s, off);
    if (lane == 0) red[w] = s;
    __syncthreads();
    if (tid == 0) {
        float tot = 0.f;
#pragma unroll
        for (int i = 0; i < 8; i++) tot += red[i];
        bcast = tot * (1.0f / Dm);
    }
    __syncthreads();
    const float mean = bcast;

    float d0 = v0 - mean, d1 = v1 - mean, d2 = v2 - mean, d3 = v3 - mean;
    float ss = d0 * d0 + d1 * d1 + d2 * d2 + d3 * d3;
#pragma unroll
    for (int off = 16; off; off >>= 1) ss += __shfl_xor_sync(0xffffffffu, ss, off);
    if (lane == 0) red[w] = ss;
    __syncthreads();
    if (tid == 0) {
        float tot = 0.f;
#pragma unroll
        for (int i = 0; i < 8; i++) tot += red[i];
        bcast = rsqrtf(tot * (1.0f / Dm) + 1e-5f);
    }
    __syncthreads();
    const float rstd = bcast;

    const int c = tid * 4;
    float4 o;
    o.x = d0 * rstd * g[c + 0] + be[c + 0];
    o.y = d1 * rstd * g[c + 1] + be[c + 1];
    o.z = d2 * rstd * g[c + 2] + be[c + 2];
    o.w = d3 * rstd * g[c + 3] + be[c + 3];
    ((float4*)(out + (size_t)row * Dm))[tid] = o;
}

// ---------------- orchestration --------------------------------------------
extern "C" void kernel_launch(void* const* d_in, const int* in_sizes, int n_in,
                              void* d_out, int out_size)
{
    const float* x            = (const float*)d_in[0];
    const unsigned char* mask = (const unsigned char*)d_in[1];
    const float* Wq  = (const float*)d_in[2];
    const float* bq  = (const float*)d_in[3];
    const float* Wk  = (const float*)d_in[4];
    const float* bk  = (const float*)d_in[5];
    const float* Wv  = (const float*)d_in[6];
    const float* bv  = (const float*)d_in[7];
    const float* Wo  = (const float*)d_in[8];
    const float* bo  = (const float*)d_in[9];
    const float* ln1g = (const float*)d_in[10];
    const float* ln1b = (const float*)d_in[11];
    const float* W1  = (const float*)d_in[12];
    const float* b1  = (const float*)d_in[13];
    const float* W2  = (const float*)d_in[14];
    const float* b2  = (const float*)d_in[15];
    const float* ln2g = (const float*)d_in[16];
    const float* ln2b = (const float*)d_in[17];
    float* out = (float*)d_out;

    float *h, *q, *k, *v, *ctx, *tmp, *ff;
    cudaGetSymbolAddress((void**)&h,   g_h);
    cudaGetSymbolAddress((void**)&q,   g_q);
    cudaGetSymbolAddress((void**)&k,   g_kb);
    cudaGetSymbolAddress((void**)&v,   g_vb);
    cudaGetSymbolAddress((void**)&ctx, g_ctx);
    cudaGetSymbolAddress((void**)&tmp, g_tmp);
    cudaGetSymbolAddress((void**)&ff,  g_ff);

    copy_kernel<<<(MROWS * Dm / 4) / 256, 256>>>((float4*)h, (const float4*)x);

    dim3 g1(Dm / 128, MROWS / 128);      // (8, 16)  N=1024 GEMMs
    dim3 g2(DHm / 128, MROWS / 128);     // (32, 16) N=4096 GEMM
    dim3 ga(Sm / 64, NHm, NB);           // (16, 16, 2) attention

    for (int l = 0; l < NL; l++) {
        const float* Wq_l = Wq + (size_t)l * Dm * Dm;
        const float* Wk_l = Wk + (size_t)l * Dm * Dm;
        const float* Wv_l = Wv + (size_t)l * Dm * Dm;
        const float* Wo_l = Wo + (size_t)l * Dm * Dm;
        const float* W1_l = W1 + (size_t)l * Dm * DHm;
        const float* W2_l = W2 + (size_t)l * DHm * Dm;

        sgemm_kernel<<<g1, 256>>>(h, Wq_l, bq + (size_t)l * Dm, q, MROWS, Dm, Dm, 0);
        sgemm_kernel<<<g1, 256>>>(h, Wk_l, bk + (size_t)l * Dm, k, MROWS, Dm, Dm, 0);
        sgemm_kernel<<<g1, 256>>>(h, Wv_l, bv + (size_t)l * Dm, v, MROWS, Dm, Dm, 0);

        attn_kernel<<<ga, 256>>>(q, k, v, mask, ctx);

        sgemm_kernel<<<g1, 256>>>(ctx, Wo_l, bo + (size_t)l * Dm, tmp, MROWS, Dm, Dm, 0);
        ln_res_kernel<<<MROWS, 256>>>(h, tmp, ln1g + (size_t)l * Dm, ln1b + (size_t)l * Dm, h);

        sgemm_kernel<<<g2, 256>>>(h, W1_l, b1 + (size_t)l * DHm, ff, MROWS, DHm, Dm, 1);
        sgemm_kernel<<<g1, 256>>>(ff, W2_l, b2 + (size_t)l * Dm, tmp, MROWS, Dm, DHm, 0);
        ln_res_kernel<<<MROWS, 256>>>(h, tmp, ln2g + (size_t)l * Dm, ln2b + (size_t)l * Dm,
                                      (l == NL - 1) ? out : h);
    }
}

// round 3
// speedup vs baseline: 1.9380x; 1.9380x over previous
#include <cuda_runtime.h>
#include <cuda_bf16.h>
#include <math.h>
#include <stdint.h>

// Problem dims (fixed by the reference)
#define Dm    1024           // d_model
#define Sm    1024           // seq len
#define NB    2              // batch
#define NHm   16             // heads
#define DQm   64             // head dim
#define DHm   4096           // ffn hidden
#define NL    6              // layers
#define MROWS (NB*Sm)        // 2048 token rows

// ---------------- scratch (device globals; no allocations allowed) --------
__device__ float g_h  [(size_t)MROWS*Dm];
__device__ float g_q  [(size_t)MROWS*Dm];
__device__ float g_kb [(size_t)MROWS*Dm];
__device__ float g_vb [(size_t)MROWS*Dm];
__device__ float g_ctx[(size_t)MROWS*Dm];
__device__ float g_tmp[(size_t)MROWS*Dm];
__device__ float g_ff [(size_t)MROWS*DHm];

// ---------------- copy x -> h ---------------------------------------------
__global__ void __launch_bounds__(256) copy_kernel(float4* __restrict__ dst,
                                                   const float4* __restrict__ src)
{
    int i = blockIdx.x * 256 + threadIdx.x;
    dst[i] = src[i];
}

// ---------------- tensor-core GEMM helpers ---------------------------------
__device__ __forceinline__ uint32_t sptr(const void* p)
{
    return (uint32_t)__cvta_generic_to_shared(p);
}

__device__ __forceinline__ void ldsm4(uint32_t* r, uint32_t addr)
{
    asm volatile("ldmatrix.sync.aligned.m8n8.x4.shared.b16 {%0,%1,%2,%3}, [%4];"
                 : "=r"(r[0]), "=r"(r[1]), "=r"(r[2]), "=r"(r[3]) : "r"(addr));
}

__device__ __forceinline__ void ldsm2t(uint32_t* r, uint32_t addr)
{
    asm volatile("ldmatrix.sync.aligned.m8n8.x2.trans.shared.b16 {%0,%1}, [%2];"
                 : "=r"(r[0]), "=r"(r[1]) : "r"(addr));
}

__device__ __forceinline__ void mma16816(float* c, const uint32_t* a, const uint32_t* b)
{
    asm volatile("mma.sync.aligned.m16n8k16.row.col.f32.bf16.bf16.f32 "
                 "{%0,%1,%2,%3}, {%4,%5,%6,%7}, {%8,%9}, {%0,%1,%2,%3};"
                 : "+f"(c[0]), "+f"(c[1]), "+f"(c[2]), "+f"(c[3])
                 : "r"(a[0]), "r"(a[1]), "r"(a[2]), "r"(a[3]),
                   "r"(b[0]), "r"(b[1]));
}

// ---------------- GEMM: C[M,N] = A[M,K] @ B[K,N] + bias (+ReLU) ------------
// bf16 split-precision (hi/lo, 3 MMAs) tensor-core kernel.
// BM=BN=128, BK=32 (fp32 k), 256 threads = 8 warps (2 m x 4 n), warp tile 64x32.
#define APAD 40    // A smem row stride (bf16 elems), 16B multiple
#define BPAD 136   // B smem row stride (bf16 elems), 16B multiple

__global__ void __launch_bounds__(256) gemm_tc_kernel(
    const float* __restrict__ A, const float* __restrict__ B,
    const float* __restrict__ bias, float* __restrict__ C,
    int M, int N, int K, int relu)
{
    __shared__ __nv_bfloat16 As_hi[128][APAD];   // [m][k]
    __shared__ __nv_bfloat16 As_lo[128][APAD];
    __shared__ __nv_bfloat16 Bs_hi[32][BPAD];    // [k][n]
    __shared__ __nv_bfloat16 Bs_lo[32][BPAD];

    const int tid  = threadIdx.x;
    const int wid  = tid >> 5, lane = tid & 31;
    const int wm   = wid >> 2;          // 0..1  (64 rows each)
    const int wn   = wid & 3;           // 0..3  (32 cols each)
    const int m0   = blockIdx.y * 128;
    const int n0   = blockIdx.x * 128;

    // staging maps (j = 0..3 covers the tile with 256 threads)
    const int arow = tid >> 3;          // +32*j  -> 0..127
    const int acol = (tid & 7) << 2;    // fp32 col in [0,32)
    const int brow = tid >> 5;          // +8*j   -> 0..31 (k)
    const int bcol = (tid & 31) << 2;   // n col in [0,128)

    float acc[4][4][4];
#pragma unroll
    for (int i = 0; i < 4; i++)
#pragma unroll
        for (int j = 0; j < 4; j++)
#pragma unroll
            for (int p = 0; p < 4; p++) acc[i][j][p] = 0.f;

    float4 pa[4], pb[4];

    // prologue: prefetch first k-tile
#pragma unroll
    for (int j = 0; j < 4; j++) {
        pa[j] = *(const float4*)(A + (size_t)(m0 + arow + 32 * j) * K + acol);
        pb[j] = *(const float4*)(B + (size_t)(brow + 8 * j) * N + n0 + bcol);
    }

    for (int k0 = 0; k0 < K; k0 += 32) {
        // stage prefetched tile into smem with hi/lo bf16 split
#pragma unroll
        for (int j = 0; j < 4; j++) {
            float va[4] = { pa[j].x, pa[j].y, pa[j].z, pa[j].w };
            float vb[4] = { pb[j].x, pb[j].y, pb[j].z, pb[j].w };
            __nv_bfloat16 ah[4], al[4], bh[4], bl[4];
#pragma unroll
            for (int e = 0; e < 4; e++) {
                ah[e] = __float2bfloat16(va[e]);
                al[e] = __float2bfloat16(va[e] - __bfloat162float(ah[e]));
                bh[e] = __float2bfloat16(vb[e]);
                bl[e] = __float2bfloat16(vb[e] - __bfloat162float(bh[e]));
            }
            int ar = arow + 32 * j;
            *(__nv_bfloat162*)&As_hi[ar][acol]     = __nv_bfloat162(ah[0], ah[1]);
            *(__nv_bfloat162*)&As_hi[ar][acol + 2] = __nv_bfloat162(ah[2], ah[3]);
            *(__nv_bfloat162*)&As_lo[ar][acol]     = __nv_bfloat162(al[0], al[1]);
            *(__nv_bfloat162*)&As_lo[ar][acol + 2] = __nv_bfloat162(al[2], al[3]);
            int br = brow + 8 * j;
            *(__nv_bfloat162*)&Bs_hi[br][bcol]     = __nv_bfloat162(bh[0], bh[1]);
            *(__nv_bfloat162*)&Bs_hi[br][bcol + 2] = __nv_bfloat162(bh[2], bh[3]);
            *(__nv_bfloat162*)&Bs_lo[br][bcol]     = __nv_bfloat162(bl[0], bl[1]);
            *(__nv_bfloat162*)&Bs_lo[br][bcol + 2] = __nv_bfloat162(bl[2], bl[3]);
        }
        __syncthreads();

        // prefetch next k-tile (overlaps MMA compute below)
        if (k0 + 32 < K) {
#pragma unroll
            for (int j = 0; j < 4; j++) {
                pa[j] = *(const float4*)(A + (size_t)(m0 + arow + 32 * j) * K + k0 + 32 + acol);
                pb[j] = *(const float4*)(B + (size_t)(k0 + 32 + brow + 8 * j) * N + n0 + bcol);
            }
        }

        // compute: two k16 steps, 3-MMA split-precision
#pragma unroll
        for (int ks = 0; ks < 2; ks++) {
            uint32_t ah[4][4], al[4][4], bh[4][2], bl[4][2];
            const int amr = (lane & 15);
            const int akc = ks * 16 + (lane >> 4) * 8;
#pragma unroll
            for (int mf = 0; mf < 4; mf++) {
                int r = wm * 64 + mf * 16 + amr;
                ldsm4(ah[mf], sptr(&As_hi[r][akc]));
                ldsm4(al[mf], sptr(&As_lo[r][akc]));
            }
            const int bkr = ks * 16 + ((lane >> 3) & 1) * 8 + (lane & 7);
#pragma unroll
            for (int nf = 0; nf < 4; nf++) {
                int c = wn * 32 + nf * 8;
                ldsm2t(bh[nf], sptr(&Bs_hi[bkr][c]));
                ldsm2t(bl[nf], sptr(&Bs_lo[bkr][c]));
            }
#pragma unroll
            for (int mf = 0; mf < 4; mf++)
#pragma unroll
                for (int nf = 0; nf < 4; nf++) {
                    mma16816(acc[mf][nf], ah[mf], bh[nf]);
                    mma16816(acc[mf][nf], ah[mf], bl[nf]);
                    mma16816(acc[mf][nf], al[mf], bh[nf]);
                }
        }
        __syncthreads();
    }

    // epilogue: bias (+relu), write C
#pragma unroll
    for (int mf = 0; mf < 4; mf++) {
        int r = m0 + wm * 64 + mf * 16 + (lane >> 2);
#pragma unroll
        for (int nf = 0; nf < 4; nf++) {
            int cc = n0 + wn * 32 + nf * 8 + 2 * (lane & 3);
            float bx = bias[cc], by = bias[cc + 1];
            float v0 = acc[mf][nf][0] + bx, v1 = acc[mf][nf][1] + by;
            float v2 = acc[mf][nf][2] + bx, v3 = acc[mf][nf][3] + by;
            if (relu) {
                v0 = fmaxf(v0, 0.f); v1 = fmaxf(v1, 0.f);
                v2 = fmaxf(v2, 0.f); v3 = fmaxf(v3, 0.f);
            }
            float2 lo = make_float2(v0, v1);
            float2 hi = make_float2(v2, v3);
            *(float2*)(C + (size_t)r * N + cc)       = lo;
            *(float2*)(C + (size_t)(r + 8) * N + cc) = hi;
        }
    }
}

// ---------------- Flash attention ------------------------------------------
__global__ void __launch_bounds__(256) attn_kernel(
    const float* __restrict__ Q, const float* __restrict__ K,
    const float* __restrict__ V, const unsigned char* __restrict__ mask,
    float* __restrict__ O)
{
    __shared__ float Qs[64][64];
    __shared__ float Kts[64][33];
    __shared__ float Vs[32][64];
    __shared__ float Ss[64][32];

    const int tid = threadIdx.x, w = tid >> 5, lane = tid & 31;
    const int qt = blockIdx.x, h = blockIdx.y, b = blockIdx.z;
    const size_t qbase = ((size_t)b * Sm + qt * 64) * Dm + h * DQm;

#pragma unroll
    for (int it = 0; it < 4; it++) {
        int i = tid + it * 256;
        int r = i >> 4, c4 = (i & 15) << 2;
        *(float4*)&Qs[r][c4] = *(const float4*)(Q + qbase + (size_t)r * Dm + c4);
    }

    float o0[8], o1[8], mr[8], lr[8];
#pragma unroll
    for (int r = 0; r < 8; r++) { o0[r] = 0.f; o1[r] = 0.f; lr[r] = 0.f; mr[r] = -1e30f; }

    const unsigned char* mrow = mask + ((size_t)b * Sm + qt * 64 + w * 8) * Sm;

    for (int k0 = 0; k0 < Sm; k0 += 32) {
#pragma unroll
        for (int it = 0; it < 2; it++) {
            int i = tid + it * 256;
            int kk = i >> 4, c4 = (i & 15) << 2;
            size_t gb = ((size_t)b * Sm + k0 + kk) * Dm + h * DQm;
            float4 kv = *(const float4*)(K + gb + c4);
            Kts[c4 + 0][kk] = kv.x;
            Kts[c4 + 1][kk] = kv.y;
            Kts[c4 + 2][kk] = kv.z;
            Kts[c4 + 3][kk] = kv.w;
            *(float4*)&Vs[kk][c4] = *(const float4*)(V + gb + c4);
        }
        __syncthreads();

        float s[8];
#pragma unroll
        for (int r = 0; r < 8; r++) s[r] = 0.f;
#pragma unroll
        for (int d4 = 0; d4 < 16; d4++) {
            float kd0 = Kts[d4 * 4 + 0][lane];
            float kd1 = Kts[d4 * 4 + 1][lane];
            float kd2 = Kts[d4 * 4 + 2][lane];
            float kd3 = Kts[d4 * 4 + 3][lane];
#pragma unroll
            for (int r = 0; r < 8; r++) {
                float4 qv = *(const float4*)&Qs[w * 8 + r][d4 * 4];
                s[r] += qv.x * kd0 + qv.y * kd1 + qv.z * kd2 + qv.w * kd3;
            }
        }

#pragma unroll
        for (int r = 0; r < 8; r++) {
            unsigned char mb = mrow[(size_t)r * Sm + k0 + lane];
            float v = mb ? -1e9f : s[r] * 0.125f;
            float mx = v;
#pragma unroll
            for (int off = 16; off; off >>= 1)
                mx = fmaxf(mx, __shfl_xor_sync(0xffffffffu, mx, off));
            float mnew = fmaxf(mr[r], mx);
            float p = __expf(v - mnew);
            float ps = p;
#pragma unroll
            for (int off = 16; off; off >>= 1)
                ps += __shfl_xor_sync(0xffffffffu, ps, off);
            float alpha = __expf(mr[r] - mnew);
            lr[r] = lr[r] * alpha + ps;
            mr[r] = mnew;
            o0[r] *= alpha;
            o1[r] *= alpha;
            Ss[w * 8 + r][lane] = p;
        }
        __syncwarp();

#pragma unroll
        for (int k4 = 0; k4 < 8; k4++) {
            float va0 = Vs[k4 * 4 + 0][lane], vb0 = Vs[k4 * 4 + 0][lane + 32];
            float va1 = Vs[k4 * 4 + 1][lane], vb1 = Vs[k4 * 4 + 1][lane + 32];
            float va2 = Vs[k4 * 4 + 2][lane], vb2 = Vs[k4 * 4 + 2][lane + 32];
            float va3 = Vs[k4 * 4 + 3][lane], vb3 = Vs[k4 * 4 + 3][lane + 32];
#pragma unroll
            for (int r = 0; r < 8; r++) {
                float4 p = *(const float4*)&Ss[w * 8 + r][k4 * 4];
                o0[r] += p.x * va0 + p.y * va1 + p.z * va2 + p.w * va3;
                o1[r] += p.x * vb0 + p.y * vb1 + p.z * vb2 + p.w * vb3;
            }
        }
        __syncthreads();
    }

#pragma unroll
    for (int r = 0; r < 8; r++) {
        float inv = 1.0f / lr[r];
        size_t orow = qbase + (size_t)(w * 8 + r) * Dm;
        O[orow + lane]      = o0[r] * inv;
        O[orow + lane + 32] = o1[r] * inv;
    }
}

// ---------------- fused residual + LayerNorm -------------------------------
__global__ void __launch_bounds__(256) ln_res_kernel(
    const float* __restrict__ x, const float* __restrict__ t,
    const float* __restrict__ g, const float* __restrict__ be,
    float* __restrict__ out)
{
    const int row = blockIdx.x, tid = threadIdx.x;
    const int w = tid >> 5, lane = tid & 31;
    __shared__ float red[8];
    __shared__ float bcast;

    float4 a = ((const float4*)(x + (size_t)row * Dm))[tid];
    float4 bb = ((const float4*)(t + (size_t)row * Dm))[tid];
    float v0 = a.x + bb.x, v1 = a.y + bb.y, v2 = a.z + bb.z, v3 = a.w + bb.w;

    float s = v0 + v1 + v2 + v3;
#pragma unroll
    for (int off = 16; off; off >>= 1) s += __shfl_xor_sync(0xffffffffu, s, off);
    if (lane == 0) red[w] = s;
    __syncthreads();
    if (tid == 0) {
        float tot = 0.f;
#pragma unroll
        for (int i = 0; i < 8; i++) tot += red[i];
        bcast = tot * (1.0f / Dm);
    }
    __syncthreads();
    const float mean = bcast;

    float d0 = v0 - mean, d1 = v1 - mean, d2 = v2 - mean, d3 = v3 - mean;
    float ss = d0 * d0 + d1 * d1 + d2 * d2 + d3 * d3;
#pragma unroll
    for (int off = 16; off; off >>= 1) ss += __shfl_xor_sync(0xffffffffu, ss, off);
    if (lane == 0) red[w] = ss;
    __syncthreads();
    if (tid == 0) {
        float tot = 0.f;
#pragma unroll
        for (int i = 0; i < 8; i++) tot += red[i];
        bcast = rsqrtf(tot * (1.0f / Dm) + 1e-5f);
    }
    __syncthreads();
    const float rstd = bcast;

    const int c = tid * 4;
    float4 o;
    o.x = d0 * rstd * g[c + 0] + be[c + 0];
    o.y = d1 * rstd * g[c + 1] + be[c + 1];
    o.z = d2 * rstd * g[c + 2] + be[c + 2];
    o.w = d3 * rstd * g[c + 3] + be[c + 3];
    ((float4*)(out + (size_t)row * Dm))[tid] = o;
}

// ---------------- orchestration --------------------------------------------
extern "C" void kernel_launch(void* const* d_in, const int* in_sizes, int n_in,
                              void* d_out, int out_size)
{
    const float* x            = (const float*)d_in[0];
    const unsigned char* mask = (const unsigned char*)d_in[1];
    const float* Wq  = (const float*)d_in[2];
    const float* bq  = (const float*)d_in[3];
    const float* Wk  = (const float*)d_in[4];
    const float* bk  = (const float*)d_in[5];
    const float* Wv  = (const float*)d_in[6];
    const float* bv  = (const float*)d_in[7];
    const float* Wo  = (const float*)d_in[8];
    const float* bo  = (const float*)d_in[9];
    const float* ln1g = (const float*)d_in[10];
    const float* ln1b = (const float*)d_in[11];
    const float* W1  = (const float*)d_in[12];
    const float* b1  = (const float*)d_in[13];
    const float* W2  = (const float*)d_in[14];
    const float* b2  = (const float*)d_in[15];
    const float* ln2g = (const float*)d_in[16];
    const float* ln2b = (const float*)d_in[17];
    float* out = (float*)d_out;

    float *h, *q, *k, *v, *ctx, *tmp, *ff;
    cudaGetSymbolAddress((void**)&h,   g_h);
    cudaGetSymbolAddress((void**)&q,   g_q);
    cudaGetSymbolAddress((void**)&k,   g_kb);
    cudaGetSymbolAddress((void**)&v,   g_vb);
    cudaGetSymbolAddress((void**)&ctx, g_ctx);
    cudaGetSymbolAddress((void**)&tmp, g_tmp);
    cudaGetSymbolAddress((void**)&ff,  g_ff);

    copy_kernel<<<(MROWS * Dm / 4) / 256, 256>>>((float4*)h, (const float4*)x);

    dim3 g1(Dm / 128, MROWS / 128);      // (8, 16)
    dim3 g2(DHm / 128, MROWS / 128);     // (32, 16)
    dim3 ga(Sm / 64, NHm, NB);           // (16, 16, 2)

    for (int l = 0; l < NL; l++) {
        const float* Wq_l = Wq + (size_t)l * Dm * Dm;
        const float* Wk_l = Wk + (size_t)l * Dm * Dm;
        const float* Wv_l = Wv + (size_t)l * Dm * Dm;
        const float* Wo_l = Wo + (size_t)l * Dm * Dm;
        const float* W1_l = W1 + (size_t)l * Dm * DHm;
        const float* W2_l = W2 + (size_t)l * DHm * Dm;

        gemm_tc_kernel<<<g1, 256>>>(h, Wq_l, bq + (size_t)l * Dm, q, MROWS, Dm, Dm, 0);
        gemm_tc_kernel<<<g1, 256>>>(h, Wk_l, bk + (size_t)l * Dm, k, MROWS, Dm, Dm, 0);
        gemm_tc_kernel<<<g1, 256>>>(h, Wv_l, bv + (size_t)l * Dm, v, MROWS, Dm, Dm, 0);

        attn_kernel<<<ga, 256>>>(q, k, v, mask, ctx);

        gemm_tc_kernel<<<g1, 256>>>(ctx, Wo_l, bo + (size_t)l * Dm, tmp, MROWS, Dm, Dm, 0);
        ln_res_kernel<<<MROWS, 256>>>(h, tmp, ln1g + (size_t)l * Dm, ln1b + (size_t)l * Dm, h);

        gemm_tc_kernel<<<g2, 256>>>(h, W1_l, b1 + (size_t)l * DHm, ff, MROWS, DHm, Dm, 1);
        gemm_tc_kernel<<<g1, 256>>>(ff, W2_l, b2 + (size_t)l * Dm, tmp, MROWS, Dm, DHm, 0);
        ln_res_kernel<<<MROWS, 256>>>(h, tmp, ln2g + (size_t)l * Dm, ln2b + (size_t)l * Dm,
                                      (l == NL - 1) ? out : h);
    }
}

// round 8
// speedup vs baseline: 2.6204x; 1.3521x over previous
#include <cuda_runtime.h>
#include <cuda_bf16.h>
#include <math.h>
#include <stdint.h>

// Problem dims (fixed by the reference)
#define Dm    1024
#define Sm    1024
#define NB    2
#define NHm   16
#define DQm   64
#define DHm   4096
#define NL    6
#define MROWS (NB*Sm)

// ---------------- scratch (device globals; no allocations allowed) --------
__device__ float g_h  [(size_t)MROWS*Dm];
__device__ float g_q  [(size_t)MROWS*Dm];
__device__ float g_kb [(size_t)MROWS*Dm];
__device__ float g_vb [(size_t)MROWS*Dm];
__device__ float g_ctx[(size_t)MROWS*Dm];
__device__ float g_tmp[(size_t)MROWS*Dm];
__device__ float g_ff [(size_t)MROWS*DHm];

// ---------------- copy x -> h ---------------------------------------------
__global__ void __launch_bounds__(256) copy_kernel(float4* __restrict__ dst,
                                                   const float4* __restrict__ src)
{
    int i = blockIdx.x * 256 + threadIdx.x;
    dst[i] = src[i];
}

// ---------------- tensor-core helpers --------------------------------------
__device__ __forceinline__ uint32_t sptr(const void* p)
{
    return (uint32_t)__cvta_generic_to_shared(p);
}
__device__ __forceinline__ void ldsm4(uint32_t* r, uint32_t addr)
{
    asm volatile("ldmatrix.sync.aligned.m8n8.x4.shared.b16 {%0,%1,%2,%3}, [%4];"
                 : "=r"(r[0]), "=r"(r[1]), "=r"(r[2]), "=r"(r[3]) : "r"(addr));
}
__device__ __forceinline__ void ldsm4t(uint32_t* r, uint32_t addr)
{
    asm volatile("ldmatrix.sync.aligned.m8n8.x4.trans.shared.b16 {%0,%1,%2,%3}, [%4];"
                 : "=r"(r[0]), "=r"(r[1]), "=r"(r[2]), "=r"(r[3]) : "r"(addr));
}
__device__ __forceinline__ void mma16816(float* c, const uint32_t* a, const uint32_t* b)
{
    asm volatile("mma.sync.aligned.m16n8k16.row.col.f32.bf16.bf16.f32 "
                 "{%0,%1,%2,%3}, {%4,%5,%6,%7}, {%8,%9}, {%0,%1,%2,%3};"
                 : "+f"(c[0]), "+f"(c[1]), "+f"(c[2]), "+f"(c[3])
                 : "r"(a[0]), "r"(a[1]), "r"(a[2]), "r"(a[3]),
                   "r"(b[0]), "r"(b[1]));
}
// pack two floats to bf16x2: lo = a, hi = b
__device__ __forceinline__ uint32_t packbf(float a, float b)
{
    uint32_t d;
    asm volatile("cvt.rn.bf16x2.f32 %0, %1, %2;" : "=r"(d) : "f"(b), "f"(a));
    return d;
}
__device__ __forceinline__ float bf16val(float x)   // round-trip through bf16
{
    return __bfloat162float(__float2bfloat16(x));
}

// ---------------- GEMM: C = A @ B + bias (+ReLU) ---------------------------
// split-bf16 (hi/lo, 3 MMA), BM=BN=128, BK=16, double-buffered STATIC smem.
#define APAD 24          // A row stride (bf16): 16 data + 8 pad
#define BPAD 136         // B row stride (bf16): 128 data + 8 pad
#define SZ_A (128*APAD)  // 3072
#define SZ_B (16*BPAD)   // 2176

__global__ void __launch_bounds__(256) gemm_tc_kernel(
    const float* __restrict__ A, const float* __restrict__ B,
    const float* __restrict__ bias, float* __restrict__ C,
    int M, int N, int K, int relu)
{
    __shared__ __nv_bfloat16 Ahs[2][SZ_A];
    __shared__ __nv_bfloat16 Als[2][SZ_A];
    __shared__ __nv_bfloat16 Bhs[2][SZ_B];
    __shared__ __nv_bfloat16 Bls[2][SZ_B];

    const int tid  = threadIdx.x;
    const int wid  = tid >> 5, lane = tid & 31;
    const int wm   = wid >> 2;          // 0..1, 64 rows each
    const int wn   = wid & 3;           // 0..3, 32 cols each
    const int m0   = blockIdx.y * 128;
    const int n0   = blockIdx.x * 128;

    const int arow = tid >> 2;          // 0..63 (+64p)
    const int acol = (tid & 3) << 2;    // 0,4,8,12
    const int brow = tid >> 5;          // 0..7 (+8p)
    const int bcol = (tid & 31) << 2;   // 0..124

    float acc[4][4][4];
#pragma unroll
    for (int i = 0; i < 4; i++)
#pragma unroll
        for (int j = 0; j < 4; j++)
#pragma unroll
            for (int p = 0; p < 4; p++) acc[i][j][p] = 0.f;

    float4 pa[2], pb[2];
#pragma unroll
    for (int p = 0; p < 2; p++) {
        pa[p] = *(const float4*)(A + (size_t)(m0 + arow + 64 * p) * K + acol);
        pb[p] = *(const float4*)(B + (size_t)(brow + 8 * p) * N + n0 + bcol);
    }

    const int nt = K >> 4;
    for (int it = 0; it < nt; it++) {
        __nv_bfloat16* Ah = Ahs[it & 1];
        __nv_bfloat16* Al = Als[it & 1];
        __nv_bfloat16* Bh = Bhs[it & 1];
        __nv_bfloat16* Bl = Bls[it & 1];

        // stage prefetched tile (hi/lo split)
#pragma unroll
        for (int p = 0; p < 2; p++) {
            float va[4] = { pa[p].x, pa[p].y, pa[p].z, pa[p].w };
            float vb[4] = { pb[p].x, pb[p].y, pb[p].z, pb[p].w };
            int ar = (arow + 64 * p) * APAD + acol;
            int br = (brow + 8 * p) * BPAD + bcol;
#pragma unroll
            for (int e = 0; e < 4; e += 2) {
                float h0 = bf16val(va[e]),   h1 = bf16val(va[e+1]);
                *(uint32_t*)&Ah[ar + e] = packbf(h0, h1);
                *(uint32_t*)&Al[ar + e] = packbf(va[e] - h0, va[e+1] - h1);
                float g0 = bf16val(vb[e]),   g1 = bf16val(vb[e+1]);
                *(uint32_t*)&Bh[br + e] = packbf(g0, g1);
                *(uint32_t*)&Bl[br + e] = packbf(vb[e] - g0, vb[e+1] - g1);
            }
        }
        __syncthreads();

        // prefetch next tile (overlaps MMA below)
        if (it + 1 < nt) {
            int k0 = (it + 1) << 4;
#pragma unroll
            for (int p = 0; p < 2; p++) {
                pa[p] = *(const float4*)(A + (size_t)(m0 + arow + 64 * p) * K + k0 + acol);
                pb[p] = *(const float4*)(B + (size_t)(k0 + brow + 8 * p) * N + n0 + bcol);
            }
        }

        // compute one k16 step
        uint32_t ah[4][4], al[4][4], bh4[2][4], bl4[2][4];
        const int amr = lane & 15;
        const int akc = (lane >> 4) * 8;
#pragma unroll
        for (int mf = 0; mf < 4; mf++) {
            int r = (wm * 64 + mf * 16 + amr) * APAD + akc;
            ldsm4(ah[mf], sptr(Ah + r));
            ldsm4(al[mf], sptr(Al + r));
        }
        // B frags: x4 trans loads 2 n8 frags per call
#pragma unroll
        for (int n16 = 0; n16 < 2; n16++) {
            int off = amr * BPAD + wn * 32 + n16 * 16 + akc;
            ldsm4t(bh4[n16], sptr(Bh + off));
            ldsm4t(bl4[n16], sptr(Bl + off));
        }
#pragma unroll
        for (int mf = 0; mf < 4; mf++)
#pragma unroll
            for (int n16 = 0; n16 < 2; n16++)
#pragma unroll
                for (int j = 0; j < 2; j++) {
                    float* c = acc[mf][2 * n16 + j];
                    mma16816(c, ah[mf], &bh4[n16][2 * j]);
                    mma16816(c, ah[mf], &bl4[n16][2 * j]);
                    mma16816(c, al[mf], &bh4[n16][2 * j]);
                }
    }

    // epilogue
#pragma unroll
    for (int mf = 0; mf < 4; mf++) {
        int r = m0 + wm * 64 + mf * 16 + (lane >> 2);
#pragma unroll
        for (int nf = 0; nf < 4; nf++) {
            int cc = n0 + wn * 32 + nf * 8 + 2 * (lane & 3);
            float bx = bias[cc], by = bias[cc + 1];
            float v0 = acc[mf][nf][0] + bx, v1 = acc[mf][nf][1] + by;
            float v2 = acc[mf][nf][2] + bx, v3 = acc[mf][nf][3] + by;
            if (relu) {
                v0 = fmaxf(v0, 0.f); v1 = fmaxf(v1, 0.f);
                v2 = fmaxf(v2, 0.f); v3 = fmaxf(v3, 0.f);
            }
            *(float2*)(C + (size_t)r * N + cc)       = make_float2(v0, v1);
            *(float2*)(C + (size_t)(r + 8) * N + cc) = make_float2(v2, v3);
        }
    }
}

// ---------------- tensor-core flash attention -------------------------------
// grid (S/128, H, B), 256 threads = 8 warps; warp w owns q-rows [16w,16w+16).
// Q fragments held in registers (loaded straight from gmem); KV tile 32 rows,
// double-buffered static smem; mask bytes read directly from gmem.
#define QPAD 72
#define KVSZ (32*QPAD)

__global__ void __launch_bounds__(256) attn_tc_kernel(
    const float* __restrict__ Q, const float* __restrict__ K,
    const float* __restrict__ V, const unsigned char* __restrict__ mask,
    float* __restrict__ O)
{
    __shared__ __nv_bfloat16 Khs[2][KVSZ];
    __shared__ __nv_bfloat16 Kls[2][KVSZ];
    __shared__ __nv_bfloat16 Vhs[2][KVSZ];
    __shared__ __nv_bfloat16 Vls[2][KVSZ];

    const int tid = threadIdx.x, w = tid >> 5, lane = tid & 31;
    const int qt = blockIdx.x, h = blockIdx.y, b = blockIdx.z;
    const int qr0 = qt * 128;
    const size_t hoff = (size_t)h * DQm;

    const int gr = lane >> 2;        // row-in-16 (and +8)
    const int gc = (lane & 3) * 2;   // col pair base

    // ---- Q fragments straight from gmem (hi/lo) ----
    uint32_t qfh[4][4], qfl[4][4];
    {
        size_t qrow0 = (size_t)(b * Sm + qr0 + w * 16 + gr) * Dm + hoff;
        size_t qrow1 = qrow0 + 8 * (size_t)Dm;
#pragma unroll
        for (int kf = 0; kf < 4; kf++) {
            float2 q00 = *(const float2*)(Q + qrow0 + kf * 16 + gc);
            float2 q10 = *(const float2*)(Q + qrow1 + kf * 16 + gc);
            float2 q01 = *(const float2*)(Q + qrow0 + kf * 16 + gc + 8);
            float2 q11 = *(const float2*)(Q + qrow1 + kf * 16 + gc + 8);
            float h0 = bf16val(q00.x), h1 = bf16val(q00.y);
            float h2 = bf16val(q10.x), h3 = bf16val(q10.y);
            float h4 = bf16val(q01.x), h5 = bf16val(q01.y);
            float h6 = bf16val(q11.x), h7 = bf16val(q11.y);
            qfh[kf][0] = packbf(h0, h1);
            qfh[kf][1] = packbf(h2, h3);
            qfh[kf][2] = packbf(h4, h5);
            qfh[kf][3] = packbf(h6, h7);
            qfl[kf][0] = packbf(q00.x - h0, q00.y - h1);
            qfl[kf][1] = packbf(q10.x - h2, q10.y - h3);
            qfl[kf][2] = packbf(q01.x - h4, q01.y - h5);
            qfl[kf][3] = packbf(q11.x - h6, q11.y - h7);
        }
    }

    float oacc[8][4];
#pragma unroll
    for (int nf = 0; nf < 8; nf++)
#pragma unroll
        for (int p = 0; p < 4; p++) oacc[nf][p] = 0.f;
    float mrow0 = -1e30f, mrow1 = -1e30f, lrow0 = 0.f, lrow1 = 0.f;

    const unsigned char* mp0 = mask + (size_t)(b * Sm + qr0 + w * 16 + gr) * Sm;
    const unsigned char* mp1 = mp0 + 8 * (size_t)Sm;

    // staging map: i = tid + 256j; r = i>>4 (0..31), c4 = (i&15)*4
    const int sr  = tid >> 4;
    const int sc4 = (tid & 15) << 2;

    // prefetch first KV tile
    float4 pk[2], pv[2];
#pragma unroll
    for (int j = 0; j < 2; j++) {
        size_t gb = ((size_t)(b * Sm + sr + 16 * j)) * Dm + hoff + sc4;
        pk[j] = *(const float4*)(K + gb);
        pv[j] = *(const float4*)(V + gb);
    }

    const int NT = Sm / 32;
    for (int it = 0; it < NT; it++) {
        __nv_bfloat16* Kh = Khs[it & 1];
        __nv_bfloat16* Kl = Kls[it & 1];
        __nv_bfloat16* Vh = Vhs[it & 1];
        __nv_bfloat16* Vl = Vls[it & 1];

        // ---- stage KV tile (hi/lo split) ----
#pragma unroll
        for (int j = 0; j < 2; j++) {
            int off = (sr + 16 * j) * QPAD + sc4;
            float a[4] = { pk[j].x, pk[j].y, pk[j].z, pk[j].w };
            float c[4] = { pv[j].x, pv[j].y, pv[j].z, pv[j].w };
#pragma unroll
            for (int e = 0; e < 4; e += 2) {
                float h0 = bf16val(a[e]), h1 = bf16val(a[e+1]);
                *(uint32_t*)&Kh[off + e] = packbf(h0, h1);
                *(uint32_t*)&Kl[off + e] = packbf(a[e] - h0, a[e+1] - h1);
                float g0 = bf16val(c[e]), g1 = bf16val(c[e+1]);
                *(uint32_t*)&Vh[off + e] = packbf(g0, g1);
                *(uint32_t*)&Vl[off + e] = packbf(c[e] - g0, c[e+1] - g1);
            }
        }
        __syncthreads();

        // prefetch next KV tile
        if (it + 1 < NT) {
            int kt = (it + 1) * 32;
#pragma unroll
            for (int j = 0; j < 2; j++) {
                size_t gb = ((size_t)(b * Sm + kt + sr + 16 * j)) * Dm + hoff + sc4;
                pk[j] = *(const float4*)(K + gb);
                pv[j] = *(const float4*)(V + gb);
            }
        }

        const int kt = it * 32;

        // ---- S = Q @ K^T (split bf16), mask, scale ----
        float pf[4][4];
#pragma unroll
        for (int n16 = 0; n16 < 2; n16++) {
            float sa[4] = {0.f,0.f,0.f,0.f}, sb[4] = {0.f,0.f,0.f,0.f};
#pragma unroll
            for (int kf = 0; kf < 4; kf++) {
                uint32_t kh4[4], kl4[4];
                int off = (n16 * 16 + (lane >> 4) * 8 + (lane & 7)) * QPAD
                        + kf * 16 + ((lane >> 3) & 1) * 8;
                ldsm4(kh4, sptr(Kh + off));
                ldsm4(kl4, sptr(Kl + off));
                mma16816(sa, qfh[kf], &kh4[0]);
                mma16816(sa, qfh[kf], &kl4[0]);
                mma16816(sa, qfl[kf], &kh4[0]);
                mma16816(sb, qfh[kf], &kh4[2]);
                mma16816(sb, qfh[kf], &kl4[2]);
                mma16816(sb, qfl[kf], &kh4[2]);
            }
#pragma unroll
            for (int j = 0; j < 2; j++) {
                const float* s4 = j ? sb : sa;
                int nf = 2 * n16 + j;
                int c = kt + nf * 8 + gc;
                uchar2 m0 = *(const uchar2*)(mp0 + c);
                uchar2 m1 = *(const uchar2*)(mp1 + c);
                pf[nf][0] = m0.x ? -1e9f : s4[0] * 0.125f;
                pf[nf][1] = m0.y ? -1e9f : s4[1] * 0.125f;
                pf[nf][2] = m1.x ? -1e9f : s4[2] * 0.125f;
                pf[nf][3] = m1.y ? -1e9f : s4[3] * 0.125f;
            }
        }

        // ---- online softmax (rows gr and gr+8) ----
        float mx0 = -1e30f, mx1 = -1e30f;
#pragma unroll
        for (int nf = 0; nf < 4; nf++) {
            mx0 = fmaxf(mx0, fmaxf(pf[nf][0], pf[nf][1]));
            mx1 = fmaxf(mx1, fmaxf(pf[nf][2], pf[nf][3]));
        }
        mx0 = fmaxf(mx0, __shfl_xor_sync(0xffffffffu, mx0, 1));
        mx0 = fmaxf(mx0, __shfl_xor_sync(0xffffffffu, mx0, 2));
        mx1 = fmaxf(mx1, __shfl_xor_sync(0xffffffffu, mx1, 1));
        mx1 = fmaxf(mx1, __shfl_xor_sync(0xffffffffu, mx1, 2));
        float mn0 = fmaxf(mrow0, mx0), mn1 = fmaxf(mrow1, mx1);
        float al0 = __expf(mrow0 - mn0), al1 = __expf(mrow1 - mn1);
        mrow0 = mn0; mrow1 = mn1;

        float ps0 = 0.f, ps1 = 0.f;
#pragma unroll
        for (int nf = 0; nf < 4; nf++) {
            pf[nf][0] = __expf(pf[nf][0] - mn0);
            pf[nf][1] = __expf(pf[nf][1] - mn0);
            pf[nf][2] = __expf(pf[nf][2] - mn1);
            pf[nf][3] = __expf(pf[nf][3] - mn1);
            ps0 += pf[nf][0] + pf[nf][1];
            ps1 += pf[nf][2] + pf[nf][3];
        }
        ps0 += __shfl_xor_sync(0xffffffffu, ps0, 1);
        ps0 += __shfl_xor_sync(0xffffffffu, ps0, 2);
        ps1 += __shfl_xor_sync(0xffffffffu, ps1, 1);
        ps1 += __shfl_xor_sync(0xffffffffu, ps1, 2);
        lrow0 = lrow0 * al0 + ps0;
        lrow1 = lrow1 * al1 + ps1;
#pragma unroll
        for (int nf = 0; nf < 8; nf++) {
            oacc[nf][0] *= al0; oacc[nf][1] *= al0;
            oacc[nf][2] *= al1; oacc[nf][3] *= al1;
        }

        // ---- P fragments (C->A mapping), hi/lo split; kf = 0..1 over k32 ----
        uint32_t pAh[2][4], pAl[2][4];
#pragma unroll
        for (int kf = 0; kf < 2; kf++) {
            float a0 = pf[2*kf][0],   a1 = pf[2*kf][1];
            float a2 = pf[2*kf][2],   a3 = pf[2*kf][3];
            float b0 = pf[2*kf+1][0], b1 = pf[2*kf+1][1];
            float b2 = pf[2*kf+1][2], b3 = pf[2*kf+1][3];
            float h0 = bf16val(a0), h1 = bf16val(a1);
            float h2 = bf16val(a2), h3 = bf16val(a3);
            float h4 = bf16val(b0), h5 = bf16val(b1);
            float h6 = bf16val(b2), h7 = bf16val(b3);
            pAh[kf][0] = packbf(h0, h1);
            pAh[kf][1] = packbf(h2, h3);
            pAh[kf][2] = packbf(h4, h5);
            pAh[kf][3] = packbf(h6, h7);
            pAl[kf][0] = packbf(a0 - h0, a1 - h1);
            pAl[kf][1] = packbf(a2 - h2, a3 - h3);
            pAl[kf][2] = packbf(b0 - h4, b1 - h5);
            pAl[kf][3] = packbf(b2 - h6, b3 - h7);
        }

        // ---- O += P @ V (split bf16) ----
#pragma unroll
        for (int n16 = 0; n16 < 4; n16++) {
#pragma unroll
            for (int kf = 0; kf < 2; kf++) {
                uint32_t vh4[4], vl4[4];
                int off = (kf * 16 + (lane & 15)) * QPAD + n16 * 16 + (lane >> 4) * 8;
                ldsm4t(vh4, sptr(Vh + off));
                ldsm4t(vl4, sptr(Vl + off));
                float* c0 = oacc[2 * n16];
                float* c1 = oacc[2 * n16 + 1];
                mma16816(c0, pAh[kf], &vh4[0]);
                mma16816(c0, pAh[kf], &vl4[0]);
                mma16816(c0, pAl[kf], &vh4[0]);
                mma16816(c1, pAh[kf], &vh4[2]);
                mma16816(c1, pAh[kf], &vl4[2]);
                mma16816(c1, pAl[kf], &vh4[2]);
            }
        }
        // no trailing sync needed: next iteration stages the other buffer,
        // and its __syncthreads() orders compute-here vs overwrite-there.
    }

    // ---- epilogue: normalize, write ----
    float inv0 = 1.0f / lrow0, inv1 = 1.0f / lrow1;
    size_t row0 = (size_t)(b * Sm + qr0 + w * 16 + gr) * Dm + hoff;
    size_t row1 = row0 + 8 * (size_t)Dm;
#pragma unroll
    for (int nf = 0; nf < 8; nf++) {
        int c = nf * 8 + gc;
        *(float2*)(O + row0 + c) = make_float2(oacc[nf][0] * inv0, oacc[nf][1] * inv0);
        *(float2*)(O + row1 + c) = make_float2(oacc[nf][2] * inv1, oacc[nf][3] * inv1);
    }
}

// ---------------- fused residual + LayerNorm -------------------------------
__global__ void __launch_bounds__(256) ln_res_kernel(
    const float* __restrict__ x, const float* __restrict__ t,
    const float* __restrict__ g, const float* __restrict__ be,
    float* __restrict__ out)
{
    const int row = blockIdx.x, tid = threadIdx.x;
    const int w = tid >> 5, lane = tid & 31;
    __shared__ float red[8];
    __shared__ float bcast;

    float4 a = ((const float4*)(x + (size_t)row * Dm))[tid];
    float4 bb = ((const float4*)(t + (size_t)row * Dm))[tid];
    float v0 = a.x + bb.x, v1 = a.y + bb.y, v2 = a.z + bb.z, v3 = a.w + bb.w;

    float s = v0 + v1 + v2 + v3;
#pragma unroll
    for (int off = 16; off; off >>= 1) s += __shfl_xor_sync(0xffffffffu, s, off);
    if (lane == 0) red[w] = s;
    __syncthreads();
    if (tid == 0) {
        float tot = 0.f;
#pragma unroll
        for (int i = 0; i < 8; i++) tot += red[i];
        bcast = tot * (1.0f / Dm);
    }
    __syncthreads();
    const float mean = bcast;

    float d0 = v0 - mean, d1 = v1 - mean, d2 = v2 - mean, d3 = v3 - mean;
    float ss = d0 * d0 + d1 * d1 + d2 * d2 + d3 * d3;
#pragma unroll
    for (int off = 16; off; off >>= 1) ss += __shfl_xor_sync(0xffffffffu, ss, off);
    if (lane == 0) red[w] = ss;
    __syncthreads();
    if (tid == 0) {
        float tot = 0.f;
#pragma unroll
        for (int i = 0; i < 8; i++) tot += red[i];
        bcast = rsqrtf(tot * (1.0f / Dm) + 1e-5f);
    }
    __syncthreads();
    const float rstd = bcast;

    const int c = tid * 4;
    float4 o;
    o.x = d0 * rstd * g[c + 0] + be[c + 0];
    o.y = d1 * rstd * g[c + 1] + be[c + 1];
    o.z = d2 * rstd * g[c + 2] + be[c + 2];
    o.w = d3 * rstd * g[c + 3] + be[c + 3];
    ((float4*)(out + (size_t)row * Dm))[tid] = o;
}

// ---------------- orchestration --------------------------------------------
extern "C" void kernel_launch(void* const* d_in, const int* in_sizes, int n_in,
                              void* d_out, int out_size)
{
    const float* x            = (const float*)d_in[0];
    const unsigned char* mask = (const unsigned char*)d_in[1];
    const float* Wq  = (const float*)d_in[2];
    const float* bq  = (const float*)d_in[3];
    const float* Wk  = (const float*)d_in[4];
    const float* bk  = (const float*)d_in[5];
    const float* Wv  = (const float*)d_in[6];
    const float* bv  = (const float*)d_in[7];
    const float* Wo  = (const float*)d_in[8];
    const float* bo  = (const float*)d_in[9];
    const float* ln1g = (const float*)d_in[10];
    const float* ln1b = (const float*)d_in[11];
    const float* W1  = (const float*)d_in[12];
    const float* b1  = (const float*)d_in[13];
    const float* W2  = (const float*)d_in[14];
    const float* b2  = (const float*)d_in[15];
    const float* ln2g = (const float*)d_in[16];
    const float* ln2b = (const float*)d_in[17];
    float* out = (float*)d_out;

    float *h, *q, *k, *v, *ctx, *tmp, *ff;
    cudaGetSymbolAddress((void**)&h,   g_h);
    cudaGetSymbolAddress((void**)&q,   g_q);
    cudaGetSymbolAddress((void**)&k,   g_kb);
    cudaGetSymbolAddress((void**)&v,   g_vb);
    cudaGetSymbolAddress((void**)&ctx, g_ctx);
    cudaGetSymbolAddress((void**)&tmp, g_tmp);
    cudaGetSymbolAddress((void**)&ff,  g_ff);

    copy_kernel<<<(MROWS * Dm / 4) / 256, 256>>>((float4*)h, (const float4*)x);

    dim3 g1(Dm / 128, MROWS / 128);      // (8, 16)
    dim3 g2(DHm / 128, MROWS / 128);     // (32, 16)
    dim3 ga(Sm / 128, NHm, NB);          // (8, 16, 2)

    for (int l = 0; l < NL; l++) {
        const float* Wq_l = Wq + (size_t)l * Dm * Dm;
        const float* Wk_l = Wk + (size_t)l * Dm * Dm;
        const float* Wv_l = Wv + (size_t)l * Dm * Dm;
        const float* Wo_l = Wo + (size_t)l * Dm * Dm;
        const float* W1_l = W1 + (size_t)l * Dm * DHm;
        const float* W2_l = W2 + (size_t)l * DHm * Dm;

        gemm_tc_kernel<<<g1, 256>>>(h, Wq_l, bq + (size_t)l * Dm, q, MROWS, Dm, Dm, 0);
        gemm_tc_kernel<<<g1, 256>>>(h, Wk_l, bk + (size_t)l * Dm, k, MROWS, Dm, Dm, 0);
        gemm_tc_kernel<<<g1, 256>>>(h, Wv_l, bv + (size_t)l * Dm, v, MROWS, Dm, Dm, 0);

        attn_tc_kernel<<<ga, 256>>>(q, k, v, mask, ctx);

        gemm_tc_kernel<<<g1, 256>>>(ctx, Wo_l, bo + (size_t)l * Dm, tmp, MROWS, Dm, Dm, 0);
        ln_res_kernel<<<MROWS, 256>>>(h, tmp, ln1g + (size_t)l * Dm, ln1b + (size_t)l * Dm, h);

        gemm_tc_kernel<<<g2, 256>>>(h, W1_l, b1 + (size_t)l * DHm, ff, MROWS, DHm, Dm, 1);
        gemm_tc_kernel<<<g1, 256>>>(ff, W2_l, b2 + (size_t)l * Dm, tmp, MROWS, Dm, DHm, 0);
        ln_res_kernel<<<MROWS, 256>>>(h, tmp, ln2g + (size_t)l * Dm, ln2b + (size_t)l * Dm,
                                      (l == NL - 1) ? out : h);
    }
}

// round 13
// speedup vs baseline: 2.9091x; 1.1102x over previous
#include <cuda_runtime.h>
#include <cuda_bf16.h>
#include <math.h>
#include <stdint.h>

// Problem dims (fixed by the reference)
#define Dm    1024
#define Sm    1024
#define NB    2
#define NHm   16
#define DQm   64
#define DHm   4096
#define NL    6
#define MROWS (NB*Sm)

// ---------------- scratch (device globals; no allocations allowed) --------
__device__ float g_h  [(size_t)MROWS*Dm];
__device__ float g_q  [(size_t)MROWS*Dm];
__device__ float g_kb [(size_t)MROWS*Dm];
__device__ float g_vb [(size_t)MROWS*Dm];
__device__ float g_ctx[(size_t)MROWS*Dm];
__device__ float g_tmp[(size_t)MROWS*Dm];
__device__ float g_ff [(size_t)MROWS*DHm];

// ---------------- copy x -> h ---------------------------------------------
__global__ void __launch_bounds__(256) copy_kernel(float4* __restrict__ dst,
                                                   const float4* __restrict__ src)
{
    int i = blockIdx.x * 256 + threadIdx.x;
    dst[i] = src[i];
}

// ---------------- tensor-core helpers --------------------------------------
__device__ __forceinline__ uint32_t sptr(const void* p)
{
    return (uint32_t)__cvta_generic_to_shared(p);
}
__device__ __forceinline__ void ldsm4(uint32_t* r, uint32_t addr)
{
    asm volatile("ldmatrix.sync.aligned.m8n8.x4.shared.b16 {%0,%1,%2,%3}, [%4];"
                 : "=r"(r[0]), "=r"(r[1]), "=r"(r[2]), "=r"(r[3]) : "r"(addr));
}
__device__ __forceinline__ void ldsm4t(uint32_t* r, uint32_t addr)
{
    asm volatile("ldmatrix.sync.aligned.m8n8.x4.trans.shared.b16 {%0,%1,%2,%3}, [%4];"
                 : "=r"(r[0]), "=r"(r[1]), "=r"(r[2]), "=r"(r[3]) : "r"(addr));
}
__device__ __forceinline__ void mma16816(float* c, const uint32_t* a, const uint32_t* b)
{
    asm volatile("mma.sync.aligned.m16n8k16.row.col.f32.bf16.bf16.f32 "
                 "{%0,%1,%2,%3}, {%4,%5,%6,%7}, {%8,%9}, {%0,%1,%2,%3};"
                 : "+f"(c[0]), "+f"(c[1]), "+f"(c[2]), "+f"(c[3])
                 : "r"(a[0]), "r"(a[1]), "r"(a[2]), "r"(a[3]),
                   "r"(b[0]), "r"(b[1]));
}
__device__ __forceinline__ uint32_t packbf(float a, float b)
{
    uint32_t d;
    asm volatile("cvt.rn.bf16x2.f32 %0, %1, %2;" : "=r"(d) : "f"(b), "f"(a));
    return d;
}
__device__ __forceinline__ float bf16val(float x)
{
    return __bfloat162float(__float2bfloat16(x));
}

// ---------------- GEMM (BM=128) — round-8 passer, verbatim ------------------
// C = A @ B + bias (+ReLU); split-bf16 (hi/lo, 3 MMA); BK=16 double-buffered.
#define APAD 24
#define BPAD 136
#define SZ_A (128*APAD)
#define SZ_B (16*BPAD)

__global__ void __launch_bounds__(256) gemm_tc_kernel(
    const float* __restrict__ A, const float* __restrict__ B,
    const float* __restrict__ bias, float* __restrict__ C,
    int M, int N, int K, int relu)
{
    __shared__ __nv_bfloat16 Ahs[2][SZ_A];
    __shared__ __nv_bfloat16 Als[2][SZ_A];
    __shared__ __nv_bfloat16 Bhs[2][SZ_B];
    __shared__ __nv_bfloat16 Bls[2][SZ_B];

    const int tid  = threadIdx.x;
    const int wid  = tid >> 5, lane = tid & 31;
    const int wm   = wid >> 2;
    const int wn   = wid & 3;
    const int m0   = blockIdx.y * 128;
    const int n0   = blockIdx.x * 128;

    const int arow = tid >> 2;
    const int acol = (tid & 3) << 2;
    const int brow = tid >> 5;
    const int bcol = (tid & 31) << 2;

    float acc[4][4][4];
#pragma unroll
    for (int i = 0; i < 4; i++)
#pragma unroll
        for (int j = 0; j < 4; j++)
#pragma unroll
            for (int p = 0; p < 4; p++) acc[i][j][p] = 0.f;

    float4 pa[2], pb[2];
#pragma unroll
    for (int p = 0; p < 2; p++) {
        pa[p] = *(const float4*)(A + (size_t)(m0 + arow + 64 * p) * K + acol);
        pb[p] = *(const float4*)(B + (size_t)(brow + 8 * p) * N + n0 + bcol);
    }

    const int nt = K >> 4;
    for (int it = 0; it < nt; it++) {
        __nv_bfloat16* Ah = Ahs[it & 1];
        __nv_bfloat16* Al = Als[it & 1];
        __nv_bfloat16* Bh = Bhs[it & 1];
        __nv_bfloat16* Bl = Bls[it & 1];

#pragma unroll
        for (int p = 0; p < 2; p++) {
            float va[4] = { pa[p].x, pa[p].y, pa[p].z, pa[p].w };
            float vb[4] = { pb[p].x, pb[p].y, pb[p].z, pb[p].w };
            int ar = (arow + 64 * p) * APAD + acol;
            int br = (brow + 8 * p) * BPAD + bcol;
#pragma unroll
            for (int e = 0; e < 4; e += 2) {
                float h0 = bf16val(va[e]),   h1 = bf16val(va[e+1]);
                *(uint32_t*)&Ah[ar + e] = packbf(h0, h1);
                *(uint32_t*)&Al[ar + e] = packbf(va[e] - h0, va[e+1] - h1);
                float g0 = bf16val(vb[e]),   g1 = bf16val(vb[e+1]);
                *(uint32_t*)&Bh[br + e] = packbf(g0, g1);
                *(uint32_t*)&Bl[br + e] = packbf(vb[e] - g0, vb[e+1] - g1);
            }
        }
        __syncthreads();

        if (it + 1 < nt) {
            int k0 = (it + 1) << 4;
#pragma unroll
            for (int p = 0; p < 2; p++) {
                pa[p] = *(const float4*)(A + (size_t)(m0 + arow + 64 * p) * K + k0 + acol);
                pb[p] = *(const float4*)(B + (size_t)(k0 + brow + 8 * p) * N + n0 + bcol);
            }
        }

        uint32_t ah[4][4], al[4][4], bh4[2][4], bl4[2][4];
        const int amr = lane & 15;
        const int akc = (lane >> 4) * 8;
#pragma unroll
        for (int mf = 0; mf < 4; mf++) {
            int r = (wm * 64 + mf * 16 + amr) * APAD + akc;
            ldsm4(ah[mf], sptr(Ah + r));
            ldsm4(al[mf], sptr(Al + r));
        }
#pragma unroll
        for (int n16 = 0; n16 < 2; n16++) {
            int off = amr * BPAD + wn * 32 + n16 * 16 + akc;
            ldsm4t(bh4[n16], sptr(Bh + off));
            ldsm4t(bl4[n16], sptr(Bl + off));
        }
#pragma unroll
        for (int mf = 0; mf < 4; mf++)
#pragma unroll
            for (int n16 = 0; n16 < 2; n16++)
#pragma unroll
                for (int j = 0; j < 2; j++) {
                    float* c = acc[mf][2 * n16 + j];
                    mma16816(c, ah[mf], &bh4[n16][2 * j]);
                    mma16816(c, ah[mf], &bl4[n16][2 * j]);
                    mma16816(c, al[mf], &bh4[n16][2 * j]);
                }
    }

#pragma unroll
    for (int mf = 0; mf < 4; mf++) {
        int r = m0 + wm * 64 + mf * 16 + (lane >> 2);
#pragma unroll
        for (int nf = 0; nf < 4; nf++) {
            int cc = n0 + wn * 32 + nf * 8 + 2 * (lane & 3);
            float bx = bias[cc], by = bias[cc + 1];
            float v0 = acc[mf][nf][0] + bx, v1 = acc[mf][nf][1] + by;
            float v2 = acc[mf][nf][2] + bx, v3 = acc[mf][nf][3] + by;
            if (relu) {
                v0 = fmaxf(v0, 0.f); v1 = fmaxf(v1, 0.f);
                v2 = fmaxf(v2, 0.f); v3 = fmaxf(v3, 0.f);
            }
            *(float2*)(C + (size_t)r * N + cc)       = make_float2(v0, v1);
            *(float2*)(C + (size_t)(r + 8) * N + cc) = make_float2(v2, v3);
        }
    }
}

// ---------------- fused QKV (same body; weight/output selected per block) ---
// grid (24, 16): blockIdx.x>>3 selects q/k/v; blockIdx.x&7 is the n-tile.
__global__ void __launch_bounds__(256) qkv_kernel(
    const float* __restrict__ A,
    const float* __restrict__ Bq, const float* __restrict__ Bk, const float* __restrict__ Bv,
    const float* __restrict__ bq, const float* __restrict__ bk, const float* __restrict__ bv,
    float* __restrict__ Cq, float* __restrict__ Ck, float* __restrict__ Cv)
{
    __shared__ __nv_bfloat16 Ahs[2][SZ_A];
    __shared__ __nv_bfloat16 Als[2][SZ_A];
    __shared__ __nv_bfloat16 Bhs[2][SZ_B];
    __shared__ __nv_bfloat16 Bls[2][SZ_B];

    const int sel = blockIdx.x >> 3;
    const float* B    = (sel == 0) ? Bq : (sel == 1) ? Bk : Bv;
    const float* bias = (sel == 0) ? bq : (sel == 1) ? bk : bv;
    float*       C    = (sel == 0) ? Cq : (sel == 1) ? Ck : Cv;

    const int tid  = threadIdx.x;
    const int wid  = tid >> 5, lane = tid & 31;
    const int wm   = wid >> 2;
    const int wn   = wid & 3;
    const int m0   = blockIdx.y * 128;
    const int n0   = (blockIdx.x & 7) * 128;
    const int N = Dm, K = Dm;

    const int arow = tid >> 2;
    const int acol = (tid & 3) << 2;
    const int brow = tid >> 5;
    const int bcol = (tid & 31) << 2;

    float acc[4][4][4];
#pragma unroll
    for (int i = 0; i < 4; i++)
#pragma unroll
        for (int j = 0; j < 4; j++)
#pragma unroll
            for (int p = 0; p < 4; p++) acc[i][j][p] = 0.f;

    float4 pa[2], pb[2];
#pragma unroll
    for (int p = 0; p < 2; p++) {
        pa[p] = *(const float4*)(A + (size_t)(m0 + arow + 64 * p) * K + acol);
        pb[p] = *(const float4*)(B + (size_t)(brow + 8 * p) * N + n0 + bcol);
    }

    const int nt = K >> 4;
    for (int it = 0; it < nt; it++) {
        __nv_bfloat16* Ah = Ahs[it & 1];
        __nv_bfloat16* Al = Als[it & 1];
        __nv_bfloat16* Bh = Bhs[it & 1];
        __nv_bfloat16* Bl = Bls[it & 1];

#pragma unroll
        for (int p = 0; p < 2; p++) {
            float va[4] = { pa[p].x, pa[p].y, pa[p].z, pa[p].w };
            float vb[4] = { pb[p].x, pb[p].y, pb[p].z, pb[p].w };
            int ar = (arow + 64 * p) * APAD + acol;
            int br = (brow + 8 * p) * BPAD + bcol;
#pragma unroll
            for (int e = 0; e < 4; e += 2) {
                float h0 = bf16val(va[e]),   h1 = bf16val(va[e+1]);
                *(uint32_t*)&Ah[ar + e] = packbf(h0, h1);
                *(uint32_t*)&Al[ar + e] = packbf(va[e] - h0, va[e+1] - h1);
                float g0 = bf16val(vb[e]),   g1 = bf16val(vb[e+1]);
                *(uint32_t*)&Bh[br + e] = packbf(g0, g1);
                *(uint32_t*)&Bl[br + e] = packbf(vb[e] - g0, vb[e+1] - g1);
            }
        }
        __syncthreads();

        if (it + 1 < nt) {
            int k0 = (it + 1) << 4;
#pragma unroll
            for (int p = 0; p < 2; p++) {
                pa[p] = *(const float4*)(A + (size_t)(m0 + arow + 64 * p) * K + k0 + acol);
                pb[p] = *(const float4*)(B + (size_t)(k0 + brow + 8 * p) * N + n0 + bcol);
            }
        }

        uint32_t ah[4][4], al[4][4], bh4[2][4], bl4[2][4];
        const int amr = lane & 15;
        const int akc = (lane >> 4) * 8;
#pragma unroll
        for (int mf = 0; mf < 4; mf++) {
            int r = (wm * 64 + mf * 16 + amr) * APAD + akc;
            ldsm4(ah[mf], sptr(Ah + r));
            ldsm4(al[mf], sptr(Al + r));
        }
#pragma unroll
        for (int n16 = 0; n16 < 2; n16++) {
            int off = amr * BPAD + wn * 32 + n16 * 16 + akc;
            ldsm4t(bh4[n16], sptr(Bh + off));
            ldsm4t(bl4[n16], sptr(Bl + off));
        }
#pragma unroll
        for (int mf = 0; mf < 4; mf++)
#pragma unroll
            for (int n16 = 0; n16 < 2; n16++)
#pragma unroll
                for (int j = 0; j < 2; j++) {
                    float* c = acc[mf][2 * n16 + j];
                    mma16816(c, ah[mf], &bh4[n16][2 * j]);
                    mma16816(c, ah[mf], &bl4[n16][2 * j]);
                    mma16816(c, al[mf], &bh4[n16][2 * j]);
                }
    }

#pragma unroll
    for (int mf = 0; mf < 4; mf++) {
        int r = m0 + wm * 64 + mf * 16 + (lane >> 2);
#pragma unroll
        for (int nf = 0; nf < 4; nf++) {
            int cc = n0 + wn * 32 + nf * 8 + 2 * (lane & 3);
            float bx = bias[cc], by = bias[cc + 1];
            *(float2*)(C + (size_t)r * N + cc) =
                make_float2(acc[mf][nf][0] + bx, acc[mf][nf][1] + by);
            *(float2*)(C + (size_t)(r + 8) * N + cc) =
                make_float2(acc[mf][nf][2] + bx, acc[mf][nf][3] + by);
        }
    }
}

// ---------------- GEMM (BM=64) — higher occupancy for Wo / W2 --------------
#define SZ_A64 (64*APAD)

__global__ void __launch_bounds__(256) gemm64_kernel(
    const float* __restrict__ A, const float* __restrict__ B,
    const float* __restrict__ bias, float* __restrict__ C,
    int M, int N, int K, int relu)
{
    __shared__ __nv_bfloat16 Ahs[2][SZ_A64];
    __shared__ __nv_bfloat16 Als[2][SZ_A64];
    __shared__ __nv_bfloat16 Bhs[2][SZ_B];
    __shared__ __nv_bfloat16 Bls[2][SZ_B];

    const int tid  = threadIdx.x;
    const int wid  = tid >> 5, lane = tid & 31;
    const int wm   = wid >> 2;          // 0..1, 32 rows each
    const int wn   = wid & 3;
    const int m0   = blockIdx.y * 64;
    const int n0   = blockIdx.x * 128;

    const int arow = tid >> 2;          // 0..63 (single pass)
    const int acol = (tid & 3) << 2;
    const int brow = tid >> 5;
    const int bcol = (tid & 31) << 2;

    float acc[2][4][4];
#pragma unroll
    for (int i = 0; i < 2; i++)
#pragma unroll
        for (int j = 0; j < 4; j++)
#pragma unroll
            for (int p = 0; p < 4; p++) acc[i][j][p] = 0.f;

    float4 pa;
    float4 pb[2];
    pa = *(const float4*)(A + (size_t)(m0 + arow) * K + acol);
#pragma unroll
    for (int p = 0; p < 2; p++)
        pb[p] = *(const float4*)(B + (size_t)(brow + 8 * p) * N + n0 + bcol);

    const int nt = K >> 4;
    for (int it = 0; it < nt; it++) {
        __nv_bfloat16* Ah = Ahs[it & 1];
        __nv_bfloat16* Al = Als[it & 1];
        __nv_bfloat16* Bh = Bhs[it & 1];
        __nv_bfloat16* Bl = Bls[it & 1];

        {
            float va[4] = { pa.x, pa.y, pa.z, pa.w };
            int ar = arow * APAD + acol;
#pragma unroll
            for (int e = 0; e < 4; e += 2) {
                float h0 = bf16val(va[e]), h1 = bf16val(va[e+1]);
                *(uint32_t*)&Ah[ar + e] = packbf(h0, h1);
                *(uint32_t*)&Al[ar + e] = packbf(va[e] - h0, va[e+1] - h1);
            }
        }
#pragma unroll
        for (int p = 0; p < 2; p++) {
            float vb[4] = { pb[p].x, pb[p].y, pb[p].z, pb[p].w };
            int br = (brow + 8 * p) * BPAD + bcol;
#pragma unroll
            for (int e = 0; e < 4; e += 2) {
                float g0 = bf16val(vb[e]), g1 = bf16val(vb[e+1]);
                *(uint32_t*)&Bh[br + e] = packbf(g0, g1);
                *(uint32_t*)&Bl[br + e] = packbf(vb[e] - g0, vb[e+1] - g1);
            }
        }
        __syncthreads();

        if (it + 1 < nt) {
            int k0 = (it + 1) << 4;
            pa = *(const float4*)(A + (size_t)(m0 + arow) * K + k0 + acol);
#pragma unroll
            for (int p = 0; p < 2; p++)
                pb[p] = *(const float4*)(B + (size_t)(k0 + brow + 8 * p) * N + n0 + bcol);
        }

        uint32_t ah[2][4], al[2][4], bh4[2][4], bl4[2][4];
        const int amr = lane & 15;
        const int akc = (lane >> 4) * 8;
#pragma unroll
        for (int mf = 0; mf < 2; mf++) {
            int r = (wm * 32 + mf * 16 + amr) * APAD + akc;
            ldsm4(ah[mf], sptr(Ah + r));
            ldsm4(al[mf], sptr(Al + r));
        }
#pragma unroll
        for (int n16 = 0; n16 < 2; n16++) {
            int off = amr * BPAD + wn * 32 + n16 * 16 + akc;
            ldsm4t(bh4[n16], sptr(Bh + off));
            ldsm4t(bl4[n16], sptr(Bl + off));
        }
#pragma unroll
        for (int mf = 0; mf < 2; mf++)
#pragma unroll
            for (int n16 = 0; n16 < 2; n16++)
#pragma unroll
                for (int j = 0; j < 2; j++) {
                    float* c = acc[mf][2 * n16 + j];
                    mma16816(c, ah[mf], &bh4[n16][2 * j]);
                    mma16816(c, ah[mf], &bl4[n16][2 * j]);
                    mma16816(c, al[mf], &bh4[n16][2 * j]);
                }
    }

#pragma unroll
    for (int mf = 0; mf < 2; mf++) {
        int r = m0 + wm * 32 + mf * 16 + (lane >> 2);
#pragma unroll
        for (int nf = 0; nf < 4; nf++) {
            int cc = n0 + wn * 32 + nf * 8 + 2 * (lane & 3);
            float bx = bias[cc], by = bias[cc + 1];
            float v0 = acc[mf][nf][0] + bx, v1 = acc[mf][nf][1] + by;
            float v2 = acc[mf][nf][2] + bx, v3 = acc[mf][nf][3] + by;
            if (relu) {
                v0 = fmaxf(v0, 0.f); v1 = fmaxf(v1, 0.f);
                v2 = fmaxf(v2, 0.f); v3 = fmaxf(v3, 0.f);
            }
            *(float2*)(C + (size_t)r * N + cc)       = make_float2(v0, v1);
            *(float2*)(C + (size_t)(r + 8) * N + cc) = make_float2(v2, v3);
        }
    }
}

// ---------------- tensor-core flash attention — round-8 passer, verbatim ----
#define QPAD 72
#define KVSZ (32*QPAD)

__global__ void __launch_bounds__(256) attn_tc_kernel(
    const float* __restrict__ Q, const float* __restrict__ K,
    const float* __restrict__ V, const unsigned char* __restrict__ mask,
    float* __restrict__ O)
{
    __shared__ __nv_bfloat16 Khs[2][KVSZ];
    __shared__ __nv_bfloat16 Kls[2][KVSZ];
    __shared__ __nv_bfloat16 Vhs[2][KVSZ];
    __shared__ __nv_bfloat16 Vls[2][KVSZ];

    const int tid = threadIdx.x, w = tid >> 5, lane = tid & 31;
    const int qt = blockIdx.x, h = blockIdx.y, b = blockIdx.z;
    const int qr0 = qt * 128;
    const size_t hoff = (size_t)h * DQm;

    const int gr = lane >> 2;
    const int gc = (lane & 3) * 2;

    uint32_t qfh[4][4], qfl[4][4];
    {
        size_t qrow0 = (size_t)(b * Sm + qr0 + w * 16 + gr) * Dm + hoff;
        size_t qrow1 = qrow0 + 8 * (size_t)Dm;
#pragma unroll
        for (int kf = 0; kf < 4; kf++) {
            float2 q00 = *(const float2*)(Q + qrow0 + kf * 16 + gc);
            float2 q10 = *(const float2*)(Q + qrow1 + kf * 16 + gc);
            float2 q01 = *(const float2*)(Q + qrow0 + kf * 16 + gc + 8);
            float2 q11 = *(const float2*)(Q + qrow1 + kf * 16 + gc + 8);
            float h0 = bf16val(q00.x), h1 = bf16val(q00.y);
            float h2 = bf16val(q10.x), h3 = bf16val(q10.y);
            float h4 = bf16val(q01.x), h5 = bf16val(q01.y);
            float h6 = bf16val(q11.x), h7 = bf16val(q11.y);
            qfh[kf][0] = packbf(h0, h1);
            qfh[kf][1] = packbf(h2, h3);
            qfh[kf][2] = packbf(h4, h5);
            qfh[kf][3] = packbf(h6, h7);
            qfl[kf][0] = packbf(q00.x - h0, q00.y - h1);
            qfl[kf][1] = packbf(q10.x - h2, q10.y - h3);
            qfl[kf][2] = packbf(q01.x - h4, q01.y - h5);
            qfl[kf][3] = packbf(q11.x - h6, q11.y - h7);
        }
    }

    float oacc[8][4];
#pragma unroll
    for (int nf = 0; nf < 8; nf++)
#pragma unroll
        for (int p = 0; p < 4; p++) oacc[nf][p] = 0.f;
    float mrow0 = -1e30f, mrow1 = -1e30f, lrow0 = 0.f, lrow1 = 0.f;

    const unsigned char* mp0 = mask + (size_t)(b * Sm + qr0 + w * 16 + gr) * Sm;
    const unsigned char* mp1 = mp0 + 8 * (size_t)Sm;

    const int sr  = tid >> 4;
    const int sc4 = (tid & 15) << 2;

    float4 pk[2], pv[2];
#pragma unroll
    for (int j = 0; j < 2; j++) {
        size_t gb = ((size_t)(b * Sm + sr + 16 * j)) * Dm + hoff + sc4;
        pk[j] = *(const float4*)(K + gb);
        pv[j] = *(const float4*)(V + gb);
    }

    const int NT = Sm / 32;
    for (int it = 0; it < NT; it++) {
        __nv_bfloat16* Kh = Khs[it & 1];
        __nv_bfloat16* Kl = Kls[it & 1];
        __nv_bfloat16* Vh = Vhs[it & 1];
        __nv_bfloat16* Vl = Vls[it & 1];

#pragma unroll
        for (int j = 0; j < 2; j++) {
            int off = (sr + 16 * j) * QPAD + sc4;
            float a[4] = { pk[j].x, pk[j].y, pk[j].z, pk[j].w };
            float c[4] = { pv[j].x, pv[j].y, pv[j].z, pv[j].w };
#pragma unroll
            for (int e = 0; e < 4; e += 2) {
                float h0 = bf16val(a[e]), h1 = bf16val(a[e+1]);
                *(uint32_t*)&Kh[off + e] = packbf(h0, h1);
                *(uint32_t*)&Kl[off + e] = packbf(a[e] - h0, a[e+1] - h1);
                float g0 = bf16val(c[e]), g1 = bf16val(c[e+1]);
                *(uint32_t*)&Vh[off + e] = packbf(g0, g1);
                *(uint32_t*)&Vl[off + e] = packbf(c[e] - g0, c[e+1] - g1);
            }
        }
        __syncthreads();

        if (it + 1 < NT) {
            int kt = (it + 1) * 32;
#pragma unroll
            for (int j = 0; j < 2; j++) {
                size_t gb = ((size_t)(b * Sm + kt + sr + 16 * j)) * Dm + hoff + sc4;
                pk[j] = *(const float4*)(K + gb);
                pv[j] = *(const float4*)(V + gb);
            }
        }

        const int kt = it * 32;

        float pf[4][4];
#pragma unroll
        for (int n16 = 0; n16 < 2; n16++) {
            float sa[4] = {0.f,0.f,0.f,0.f}, sb[4] = {0.f,0.f,0.f,0.f};
#pragma unroll
            for (int kf = 0; kf < 4; kf++) {
                uint32_t kh4[4], kl4[4];
                int off = (n16 * 16 + (lane >> 4) * 8 + (lane & 7)) * QPAD
                        + kf * 16 + ((lane >> 3) & 1) * 8;
                ldsm4(kh4, sptr(Kh + off));
                ldsm4(kl4, sptr(Kl + off));
                mma16816(sa, qfh[kf], &kh4[0]);
                mma16816(sa, qfh[kf], &kl4[0]);
                mma16816(sa, qfl[kf], &kh4[0]);
                mma16816(sb, qfh[kf], &kh4[2]);
                mma16816(sb, qfh[kf], &kl4[2]);
                mma16816(sb, qfl[kf], &kh4[2]);
            }
#pragma unroll
            for (int j = 0; j < 2; j++) {
                const float* s4 = j ? sb : sa;
                int nf = 2 * n16 + j;
                int c = kt + nf * 8 + gc;
                uchar2 m0 = *(const uchar2*)(mp0 + c);
                uchar2 m1 = *(const uchar2*)(mp1 + c);
                pf[nf][0] = m0.x ? -1e9f : s4[0] * 0.125f;
                pf[nf][1] = m0.y ? -1e9f : s4[1] * 0.125f;
                pf[nf][2] = m1.x ? -1e9f : s4[2] * 0.125f;
                pf[nf][3] = m1.y ? -1e9f : s4[3] * 0.125f;
            }
        }

        float mx0 = -1e30f, mx1 = -1e30f;
#pragma unroll
        for (int nf = 0; nf < 4; nf++) {
            mx0 = fmaxf(mx0, fmaxf(pf[nf][0], pf[nf][1]));
            mx1 = fmaxf(mx1, fmaxf(pf[nf][2], pf[nf][3]));
        }
        mx0 = fmaxf(mx0, __shfl_xor_sync(0xffffffffu, mx0, 1));
        mx0 = fmaxf(mx0, __shfl_xor_sync(0xffffffffu, mx0, 2));
        mx1 = fmaxf(mx1, __shfl_xor_sync(0xffffffffu, mx1, 1));
        mx1 = fmaxf(mx1, __shfl_xor_sync(0xffffffffu, mx1, 2));
        float mn0 = fmaxf(mrow0, mx0), mn1 = fmaxf(mrow1, mx1);
        float al0 = __expf(mrow0 - mn0), al1 = __expf(mrow1 - mn1);
        mrow0 = mn0; mrow1 = mn1;

        float ps0 = 0.f, ps1 = 0.f;
#pragma unroll
        for (int nf = 0; nf < 4; nf++) {
            pf[nf][0] = __expf(pf[nf][0] - mn0);
            pf[nf][1] = __expf(pf[nf][1] - mn0);
            pf[nf][2] = __expf(pf[nf][2] - mn1);
            pf[nf][3] = __expf(pf[nf][3] - mn1);
            ps0 += pf[nf][0] + pf[nf][1];
            ps1 += pf[nf][2] + pf[nf][3];
        }
        ps0 += __shfl_xor_sync(0xffffffffu, ps0, 1);
        ps0 += __shfl_xor_sync(0xffffffffu, ps0, 2);
        ps1 += __shfl_xor_sync(0xffffffffu, ps1, 1);
        ps1 += __shfl_xor_sync(0xffffffffu, ps1, 2);
        lrow0 = lrow0 * al0 + ps0;
        lrow1 = lrow1 * al1 + ps1;
#pragma unroll
        for (int nf = 0; nf < 8; nf++) {
            oacc[nf][0] *= al0; oacc[nf][1] *= al0;
            oacc[nf][2] *= al1; oacc[nf][3] *= al1;
        }

        uint32_t pAh[2][4], pAl[2][4];
#pragma unroll
        for (int kf = 0; kf < 2; kf++) {
            float a0 = pf[2*kf][0],   a1 = pf[2*kf][1];
            float a2 = pf[2*kf][2],   a3 = pf[2*kf][3];
            float b0 = pf[2*kf+1][0], b1 = pf[2*kf+1][1];
            float b2 = pf[2*kf+1][2], b3 = pf[2*kf+1][3];
            float h0 = bf16val(a0), h1 = bf16val(a1);
            float h2 = bf16val(a2), h3 = bf16val(a3);
            float h4 = bf16val(b0), h5 = bf16val(b1);
            float h6 = bf16val(b2), h7 = bf16val(b3);
            pAh[kf][0] = packbf(h0, h1);
            pAh[kf][1] = packbf(h2, h3);
            pAh[kf][2] = packbf(h4, h5);
            pAh[kf][3] = packbf(h6, h7);
            pAl[kf][0] = packbf(a0 - h0, a1 - h1);
            pAl[kf][1] = packbf(a2 - h2, a3 - h3);
            pAl[kf][2] = packbf(b0 - h4, b1 - h5);
            pAl[kf][3] = packbf(b2 - h6, b3 - h7);
        }

#pragma unroll
        for (int n16 = 0; n16 < 4; n16++) {
#pragma unroll
            for (int kf = 0; kf < 2; kf++) {
                uint32_t vh4[4], vl4[4];
                int off = (kf * 16 + (lane & 15)) * QPAD + n16 * 16 + (lane >> 4) * 8;
                ldsm4t(vh4, sptr(Vh + off));
                ldsm4t(vl4, sptr(Vl + off));
                float* c0 = oacc[2 * n16];
                float* c1 = oacc[2 * n16 + 1];
                mma16816(c0, pAh[kf], &vh4[0]);
                mma16816(c0, pAh[kf], &vl4[0]);
                mma16816(c0, pAl[kf], &vh4[0]);
                mma16816(c1, pAh[kf], &vh4[2]);
                mma16816(c1, pAh[kf], &vl4[2]);
                mma16816(c1, pAl[kf], &vh4[2]);
            }
        }
    }

    float inv0 = 1.0f / lrow0, inv1 = 1.0f / lrow1;
    size_t row0 = (size_t)(b * Sm + qr0 + w * 16 + gr) * Dm + hoff;
    size_t row1 = row0 + 8 * (size_t)Dm;
#pragma unroll
    for (int nf = 0; nf < 8; nf++) {
        int c = nf * 8 + gc;
        *(float2*)(O + row0 + c) = make_float2(oacc[nf][0] * inv0, oacc[nf][1] * inv0);
        *(float2*)(O + row1 + c) = make_float2(oacc[nf][2] * inv1, oacc[nf][3] * inv1);
    }
}

// ---------------- fused residual + LayerNorm -------------------------------
__global__ void __launch_bounds__(256) ln_res_kernel(
    const float* __restrict__ x, const float* __restrict__ t,
    const float* __restrict__ g, const float* __restrict__ be,
    float* __restrict__ out)
{
    const int row = blockIdx.x, tid = threadIdx.x;
    const int w = tid >> 5, lane = tid & 31;
    __shared__ float red[8];
    __shared__ float bcast;

    float4 a = ((const float4*)(x + (size_t)row * Dm))[tid];
    float4 bb = ((const float4*)(t + (size_t)row * Dm))[tid];
    float v0 = a.x + bb.x, v1 = a.y + bb.y, v2 = a.z + bb.z, v3 = a.w + bb.w;

    float s = v0 + v1 + v2 + v3;
#pragma unroll
    for (int off = 16; off; off >>= 1) s += __shfl_xor_sync(0xffffffffu, s, off);
    if (lane == 0) red[w] = s;
    __syncthreads();
    if (tid == 0) {
        float tot = 0.f;
#pragma unroll
        for (int i = 0; i < 8; i++) tot += red[i];
        bcast = tot * (1.0f / Dm);
    }
    __syncthreads();
    const float mean = bcast;

    float d0 = v0 - mean, d1 = v1 - mean, d2 = v2 - mean, d3 = v3 - mean;
    float ss = d0 * d0 + d1 * d1 + d2 * d2 + d3 * d3;
#pragma unroll
    for (int off = 16; off; off >>= 1) ss += __shfl_xor_sync(0xffffffffu, ss, off);
    if (lane == 0) red[w] = ss;
    __syncthreads();
    if (tid == 0) {
        float tot = 0.f;
#pragma unroll
        for (int i = 0; i < 8; i++) tot += red[i];
        bcast = rsqrtf(tot * (1.0f / Dm) + 1e-5f);
    }
    __syncthreads();
    const float rstd = bcast;

    const int c = tid * 4;
    float4 o;
    o.x = d0 * rstd * g[c + 0] + be[c + 0];
    o.y = d1 * rstd * g[c + 1] + be[c + 1];
    o.z = d2 * rstd * g[c + 2] + be[c + 2];
    o.w = d3 * rstd * g[c + 3] + be[c + 3];
    ((float4*)(out + (size_t)row * Dm))[tid] = o;
}

// ---------------- orchestration --------------------------------------------
extern "C" void kernel_launch(void* const* d_in, const int* in_sizes, int n_in,
                              void* d_out, int out_size)
{
    const float* x            = (const float*)d_in[0];
    const unsigned char* mask = (const unsigned char*)d_in[1];
    const float* Wq  = (const float*)d_in[2];
    const float* bq  = (const float*)d_in[3];
    const float* Wk  = (const float*)d_in[4];
    const float* bk  = (const float*)d_in[5];
    const float* Wv  = (const float*)d_in[6];
    const float* bv  = (const float*)d_in[7];
    const float* Wo  = (const float*)d_in[8];
    const float* bo  = (const float*)d_in[9];
    const float* ln1g = (const float*)d_in[10];
    const float* ln1b = (const float*)d_in[11];
    const float* W1  = (const float*)d_in[12];
    const float* b1  = (const float*)d_in[13];
    const float* W2  = (const float*)d_in[14];
    const float* b2  = (const float*)d_in[15];
    const float* ln2g = (const float*)d_in[16];
    const float* ln2b = (const float*)d_in[17];
    float* out = (float*)d_out;

    float *h, *q, *k, *v, *ctx, *tmp, *ff;
    cudaGetSymbolAddress((void**)&h,   g_h);
    cudaGetSymbolAddress((void**)&q,   g_q);
    cudaGetSymbolAddress((void**)&k,   g_kb);
    cudaGetSymbolAddress((void**)&v,   g_vb);
    cudaGetSymbolAddress((void**)&ctx, g_ctx);
    cudaGetSymbolAddress((void**)&tmp, g_tmp);
    cudaGetSymbolAddress((void**)&ff,  g_ff);

    copy_kernel<<<(MROWS * Dm / 4) / 256, 256>>>((float4*)h, (const float4*)x);

    dim3 gqkv(24, MROWS / 128);          // (24, 16) fused QKV -> 384 CTAs
    dim3 g1(DHm / 128, MROWS / 128);     // (32, 16) W1
    dim3 g64(Dm / 128, MROWS / 64);      // (8, 32)  Wo / W2 (BM=64) -> 256 CTAs
    dim3 ga(Sm / 128, NHm, NB);          // (8, 16, 2)

    for (int l = 0; l < NL; l++) {
        qkv_kernel<<<gqkv, 256>>>(h,
            Wq + (size_t)l * Dm * Dm, Wk + (size_t)l * Dm * Dm, Wv + (size_t)l * Dm * Dm,
            bq + (size_t)l * Dm, bk + (size_t)l * Dm, bv + (size_t)l * Dm,
            q, k, v);

        attn_tc_kernel<<<ga, 256>>>(q, k, v, mask, ctx);

        gemm64_kernel<<<g64, 256>>>(ctx, Wo + (size_t)l * Dm * Dm,
                                    bo + (size_t)l * Dm, tmp, MROWS, Dm, Dm, 0);
        ln_res_kernel<<<MROWS, 256>>>(h, tmp, ln1g + (size_t)l * Dm, ln1b + (size_t)l * Dm, h);

        gemm_tc_kernel<<<g1, 256>>>(h, W1 + (size_t)l * Dm * DHm,
                                    b1 + (size_t)l * DHm, ff, MROWS, DHm, Dm, 1);
        gemm64_kernel<<<g64, 256>>>(ff, W2 + (size_t)l * DHm * Dm,
                                    b2 + (size_t)l * Dm, tmp, MROWS, Dm, DHm, 0);
        ln_res_kernel<<<MROWS, 256>>>(h, tmp, ln2g + (size_t)l * Dm, ln2b + (size_t)l * Dm,
                                      (l == NL - 1) ? out : h);
    }
}